// round 8
// baseline (speedup 1.0000x reference)
#include <cuda_runtime.h>
#include <math.h>

// Problem constants (fixed by setup_inputs)
#define BB   4
#define C2   512        // deep channels
#define DD   32         // d = 2*C/16
#define HWD  4096       // 64*64 deep spatial
#define OC   256        // out channels of K conv
#define CIN  256        // shallow channels
#define PIX  16384      // 128*128 shallow spatial

typedef unsigned long long ull;

// Scratch (device globals: allocation-free)
__device__ float g_maxout[BB * DD * HWD];            // [b][dd][p]
__device__ float g_qmax [BB * HWD];
__device__ float g_qmean[BB * HWD];
__device__ float g_scale[BB * HWD];                  // 1 + sigmoid(re_score)
__device__ float g_Kx[(size_t)BB * OC * PIX];        // [b][o][128*128], 64MB

// Packed fp32x2 FMA: d = a*b + d  (SASS FFMA2, 2x fp32 issue rate)
__device__ __forceinline__ void ffma2(ull& d, ull a, ull b) {
    asm("fma.rn.f32x2 %0, %1, %2, %0;" : "+l"(d) : "l"(a), "l"(b));
}
__device__ __forceinline__ void unpack2(float& lo, float& hi, ull v) {
    asm("mov.b64 {%0, %1}, %2;" : "=f"(lo), "=f"(hi) : "l"(v));
}

// ---------------------------------------------------------------------------
// Kernel 1: max_out = KSA_w @ deep + KSA_b  (per pixel), plus q (max over dd)
// and qmean (mean over dd).
// ---------------------------------------------------------------------------
__global__ void k_maxout(const float* __restrict__ deep,
                         const float* __restrict__ ksa_w,
                         const float* __restrict__ ksa_b)
{
    __shared__ float ws[32 * 256];
    int b = blockIdx.y;
    int p = blockIdx.x * 128 + threadIdx.x;

    float acc[32];
#pragma unroll
    for (int d = 0; d < 32; d++) acc[d] = ksa_b[d];

    for (int cc = 0; cc < C2; cc += 256) {
        __syncthreads();
        for (int i = threadIdx.x; i < 32 * 256; i += 128) {
            int d = i >> 8, c = i & 255;
            ws[i] = ksa_w[d * C2 + cc + c];
        }
        __syncthreads();
        const float* dptr = deep + ((size_t)b * C2 + cc) * HWD + p;
#pragma unroll 4
        for (int c = 0; c < 256; c++) {
            float x = dptr[(size_t)c * HWD];
#pragma unroll
            for (int d = 0; d < 32; d++) acc[d] += ws[d * 256 + c] * x;
        }
    }

    float mx = acc[0], sm = 0.f;
#pragma unroll
    for (int d = 0; d < 32; d++) {
        g_maxout[((size_t)b * DD + d) * HWD + p] = acc[d];
        mx = fmaxf(mx, acc[d]);
        sm += acc[d];
    }
    g_qmax [b * HWD + p] = mx;
    g_qmean[b * HWD + p] = sm * (1.f / 32.f);
}

// ---------------------------------------------------------------------------
// Kernel 2: lit (channel-scrambled flat-view dot), re_score, scale.
// ---------------------------------------------------------------------------
__global__ void k_lit(float* __restrict__ rescore_out)
{
    int b    = blockIdx.x;
    int tid  = threadIdx.x;
    int wid  = tid >> 5;
    int lane = tid & 31;
    const float* mo = g_maxout + (size_t)b * DD * HWD;
    const float* q  = g_qmax + b * HWD;

    float part = 0.f;
#pragma unroll 4
    for (int k = 0; k < 128; k++) {
        int p = lane + (k << 5);
        part += q[p] * mo[((p >> 7) << 12) + ((p & 127) << 5) + wid];
    }
#pragma unroll
    for (int off = 16; off; off >>= 1)
        part += __shfl_xor_sync(0xffffffffu, part, off);

    __shared__ float slit[32];
    if (lane == 0) slit[wid] = part * (1.f / 4096.f);
    __syncthreads();

    for (int p = tid; p < HWD; p += 1024) {
        float r = 0.f;
#pragma unroll
        for (int d = 0; d < 32; d++) r += slit[d] * mo[d * HWD + p];
        rescore_out[b * HWD + p] = r;
        g_scale[b * HWD + p] = 1.f + 1.f / (1.f + __expf(-r));
    }
}

// ---------------------------------------------------------------------------
// Kernel 3: SGEMM per batch using packed FFMA2 (fma.rn.f32x2).
// M=256, N=16384, K=256. 128x128 tiles, BK=16, 8x8 per thread, 256 threads.
// Diagonal outer-product scheme:
//   aa[ip] = (a_{2ip}, a_{2ip+1})   (natural reg pair from LDS.128)
//   bb[jp] = (b_{2jp}, b_{2jp+1})
//   bs[jp] = (b_{2jp+1}, b_{2jp})   (pre-swizzled shared tile, no MOVs)
//   accD[ip][jp] += aa*bb -> (C[2ip][2jp],   C[2ip+1][2jp+1])
//   accX[ip][jp] += aa*bs -> (C[2ip][2jp+1], C[2ip+1][2jp])
// ---------------------------------------------------------------------------
#define BM 128
#define BN 128
#define BK 16
__global__ __launch_bounds__(256, 2)
void k_sgemm(const float* __restrict__ W,
             const float* __restrict__ bias,
             const float* __restrict__ X)
{
    __shared__ float As [BK][BM + 4];   // pitch 132 floats (528B: 16B multiple)
    __shared__ float Bs [BK][BN];
    __shared__ float BsS[BK][BN];       // pairwise-swapped copy of Bs

    int b  = blockIdx.z;
    int m0 = blockIdx.y * BM;
    int n0 = blockIdx.x * BN;
    const float* Xb = X + (size_t)b * CIN * PIX;
    float*       Cb = g_Kx + (size_t)b * OC * PIX;

    int tid = threadIdx.x;
    int tx  = tid & 15;       // n direction
    int ty  = tid >> 4;       // m direction

    ull accD[4][4], accX[4][4];
#pragma unroll
    for (int i = 0; i < 4; i++)
#pragma unroll
        for (int j = 0; j < 4; j++) { accD[i][j] = 0ull; accX[i][j] = 0ull; }

    for (int k0 = 0; k0 < CIN; k0 += BK) {
        // Load A tile (128 m x 16 k), transposed into As[k][m]
#pragma unroll
        for (int r = 0; r < 2; r++) {
            int f  = tid + r * 256;          // 0..511 float4 slots
            int m  = f >> 2;                 // 0..127
            int kq = (f & 3) << 2;           // 0,4,8,12
            float4 a = *reinterpret_cast<const float4*>(W + (size_t)(m0 + m) * CIN + k0 + kq);
            As[kq + 0][m] = a.x;
            As[kq + 1][m] = a.y;
            As[kq + 2][m] = a.z;
            As[kq + 3][m] = a.w;
        }
        // Load B tile (16 k x 128 n) + swapped-pair copy
#pragma unroll
        for (int r = 0; r < 2; r++) {
            int f  = tid + r * 256;
            int k  = f >> 5;                 // 0..15
            int n4 = (f & 31) << 2;          // 0..124
            float4 v = *reinterpret_cast<const float4*>(Xb + (size_t)(k0 + k) * PIX + n0 + n4);
            *reinterpret_cast<float4*>(&Bs [k][n4]) = v;
            *reinterpret_cast<float4*>(&BsS[k][n4]) = make_float4(v.y, v.x, v.w, v.z);
        }
        __syncthreads();

#pragma unroll
        for (int k = 0; k < BK; k++) {
            ulonglong2 A0 = *reinterpret_cast<const ulonglong2*>(&As [k][ty * 8]);
            ulonglong2 A1 = *reinterpret_cast<const ulonglong2*>(&As [k][ty * 8 + 4]);
            ulonglong2 B0 = *reinterpret_cast<const ulonglong2*>(&Bs [k][tx * 8]);
            ulonglong2 B1 = *reinterpret_cast<const ulonglong2*>(&Bs [k][tx * 8 + 4]);
            ulonglong2 S0 = *reinterpret_cast<const ulonglong2*>(&BsS[k][tx * 8]);
            ulonglong2 S1 = *reinterpret_cast<const ulonglong2*>(&BsS[k][tx * 8 + 4]);
            ull aa[4] = {A0.x, A0.y, A1.x, A1.y};
            ull bb[4] = {B0.x, B0.y, B1.x, B1.y};
            ull bs[4] = {S0.x, S0.y, S1.x, S1.y};
#pragma unroll
            for (int ip = 0; ip < 4; ip++)
#pragma unroll
                for (int jp = 0; jp < 4; jp++) {
                    ffma2(accD[ip][jp], aa[ip], bb[jp]);
                    ffma2(accX[ip][jp], aa[ip], bs[jp]);
                }
        }
        __syncthreads();
    }

    // Epilogue: unscramble diagonal layout, add bias, store.
#pragma unroll
    for (int ip = 0; ip < 4; ip++) {
        float row0[8], row1[8];
#pragma unroll
        for (int jp = 0; jp < 4; jp++) {
            float dlo, dhi, xlo, xhi;
            unpack2(dlo, dhi, accD[ip][jp]);
            unpack2(xlo, xhi, accX[ip][jp]);
            row0[2 * jp]     = dlo;   // C[2ip  ][2jp  ]
            row0[2 * jp + 1] = xlo;   // C[2ip  ][2jp+1]
            row1[2 * jp]     = xhi;   // C[2ip+1][2jp  ]
            row1[2 * jp + 1] = dhi;   // C[2ip+1][2jp+1]
        }
        int mA = m0 + ty * 8 + 2 * ip;
        float bA = bias[mA], bB = bias[mA + 1];
        float* c0 = Cb + (size_t)mA * PIX + n0 + tx * 8;
        float* c1 = c0 + PIX;
        *reinterpret_cast<float4*>(c0)     = make_float4(row0[0] + bA, row0[1] + bA, row0[2] + bA, row0[3] + bA);
        *reinterpret_cast<float4*>(c0 + 4) = make_float4(row0[4] + bA, row0[5] + bA, row0[6] + bA, row0[7] + bA);
        *reinterpret_cast<float4*>(c1)     = make_float4(row1[0] + bB, row1[1] + bB, row1[2] + bB, row1[3] + bB);
        *reinterpret_cast<float4*>(c1 + 4) = make_float4(row1[4] + bB, row1[5] + bB, row1[6] + bB, row1[7] + bB);
    }
}

// ---------------------------------------------------------------------------
// Kernel 4: fused unfold(3x3, stride 2, pad 1) + softmax attention + gating.
// ---------------------------------------------------------------------------
__global__ void k_att(float* __restrict__ out)
{
    int idx = blockIdx.x * 256 + threadIdx.x;   // < B*OC*HWD
    int p = idx & (HWD - 1);
    int o = (idx >> 12) & (OC - 1);
    int b = idx >> 20;
    int y = p >> 6, x = p & 63;

    const float* base = g_Kx + ((size_t)(b * OC + o) << 14);
    float m  = g_qmean[(b << 12) + p];
    float sc = g_scale[(b << 12) + p];

    float v[9];
    int yy0 = 2 * y - 1, xx0 = 2 * x - 1;
#pragma unroll
    for (int i = 0; i < 3; i++) {
        int yy = yy0 + i;
#pragma unroll
        for (int j = 0; j < 3; j++) {
            int xx = xx0 + j;
            v[i * 3 + j] = (yy >= 0 && xx >= 0) ? base[(yy << 7) + xx] : 0.f;
        }
    }

    float L = m * v[0];
#pragma unroll
    for (int k = 1; k < 9; k++) L = fmaxf(L, m * v[k]);
    float s = 0.f, num = 0.f;
#pragma unroll
    for (int k = 0; k < 9; k++) {
        float e = __expf(m * v[k] - L);
        s   += e;
        num += e * v[k];
    }
    out[idx] = sc * (num / s);   // att * (1 + sigmoid(re_score))
}

// ---------------------------------------------------------------------------
extern "C" void kernel_launch(void* const* d_in, const int* in_sizes, int n_in,
                              void* d_out, int out_size)
{
    const float* shallow = (const float*)d_in[0];
    const float* deep    = (const float*)d_in[1];
    const float* K_w     = (const float*)d_in[2];
    const float* K_b     = (const float*)d_in[3];
    const float* KSA_w   = (const float*)d_in[4];
    const float* KSA_b   = (const float*)d_in[5];
    float* out = (float*)d_out;

    // Output layout: [B,OC,64,64] main, then [B,1,64,64] re_score.
    float* rescore_out = out + (size_t)BB * OC * HWD;

    k_maxout<<<dim3(HWD / 128, BB), 128>>>(deep, KSA_w, KSA_b);
    k_lit<<<BB, 1024>>>(rescore_out);
    k_sgemm<<<dim3(PIX / BN, OC / BM, BB), 256>>>(K_w, K_b, shallow);
    k_att<<<(BB * OC * HWD) / 256, 256>>>(out);
}

// round 10
// speedup vs baseline: 1.5562x; 1.5562x over previous
#include <cuda_runtime.h>
#include <cuda_bf16.h>
#include <math.h>
#include <stdint.h>

// Problem constants (fixed by setup_inputs)
#define BB   4
#define C2   512        // deep channels
#define DD   32         // d = 2*C/16
#define HWD  4096       // 64*64 deep spatial
#define OC   256        // out channels of K conv
#define CIN  256        // shallow channels
#define PIX  16384      // 128*128 shallow spatial

// Scratch (device globals: allocation-free)
__device__ float g_maxout[BB * DD * HWD];
__device__ float g_qmax [BB * HWD];
__device__ float g_qmean[BB * HWD];
__device__ float g_scale[BB * HWD];
__device__ float g_Kx[(size_t)BB * OC * PIX];                          // 64MB
__device__ __align__(16) __nv_bfloat16 g_Whi[OC * CIN];
__device__ __align__(16) __nv_bfloat16 g_Wlo[OC * CIN];
__device__ __align__(16) __nv_bfloat16 g_Xhi[(size_t)BB * PIX * CIN];  // [b][p][c]
__device__ __align__(16) __nv_bfloat16 g_Xlo[(size_t)BB * PIX * CIN];

// ---------------------------------------------------------------------------
// PTX helpers (all baseline sm_80+ instructions: family-safe at compute_103)
// ---------------------------------------------------------------------------
__device__ __forceinline__ uint32_t smem_u32(const void* p) {
    uint32_t a;
    asm("{ .reg .u64 t; cvta.to.shared.u64 t, %1; cvt.u32.u64 %0, t; }"
        : "=r"(a) : "l"(p));
    return a;
}
__device__ __forceinline__ void cp16(uint32_t dst, const void* src) {
    asm volatile("cp.async.cg.shared.global [%0], [%1], 16;"
                 :: "r"(dst), "l"(src) : "memory");
}
__device__ __forceinline__ void ldsm4(uint32_t* r, uint32_t addr) {
    asm volatile("ldmatrix.sync.aligned.m8n8.x4.shared.b16 {%0,%1,%2,%3}, [%4];"
                 : "=r"(r[0]), "=r"(r[1]), "=r"(r[2]), "=r"(r[3]) : "r"(addr));
}
__device__ __forceinline__ void mma_bf16(float* c, const uint32_t* a, const uint32_t* b) {
    asm volatile(
        "mma.sync.aligned.m16n8k16.row.col.f32.bf16.bf16.f32 "
        "{%0,%1,%2,%3}, {%4,%5,%6,%7}, {%8,%9}, {%0,%1,%2,%3};"
        : "+f"(c[0]), "+f"(c[1]), "+f"(c[2]), "+f"(c[3])
        : "r"(a[0]), "r"(a[1]), "r"(a[2]), "r"(a[3]), "r"(b[0]), "r"(b[1]));
}

// ---------------------------------------------------------------------------
// Kernel 1: max_out = KSA_w @ deep + KSA_b; q = max_dd; qmean = mean_dd.
// ---------------------------------------------------------------------------
__global__ void k_maxout(const float* __restrict__ deep,
                         const float* __restrict__ ksa_w,
                         const float* __restrict__ ksa_b)
{
    __shared__ float ws[32 * 256];
    int b = blockIdx.y;
    int p = blockIdx.x * 128 + threadIdx.x;

    float acc[32];
#pragma unroll
    for (int d = 0; d < 32; d++) acc[d] = ksa_b[d];

    for (int cc = 0; cc < C2; cc += 256) {
        __syncthreads();
        for (int i = threadIdx.x; i < 32 * 256; i += 128) {
            int d = i >> 8, c = i & 255;
            ws[i] = ksa_w[d * C2 + cc + c];
        }
        __syncthreads();
        const float* dptr = deep + ((size_t)b * C2 + cc) * HWD + p;
#pragma unroll 4
        for (int c = 0; c < 256; c++) {
            float x = dptr[(size_t)c * HWD];
#pragma unroll
            for (int d = 0; d < 32; d++) acc[d] += ws[d * 256 + c] * x;
        }
    }

    float mx = acc[0], sm = 0.f;
#pragma unroll
    for (int d = 0; d < 32; d++) {
        g_maxout[((size_t)b * DD + d) * HWD + p] = acc[d];
        mx = fmaxf(mx, acc[d]);
        sm += acc[d];
    }
    g_qmax [b * HWD + p] = mx;
    g_qmean[b * HWD + p] = sm * (1.f / 32.f);
}

// ---------------------------------------------------------------------------
// Kernel 2: lit (channel-scrambled flat-view), re_score, scale.
// ---------------------------------------------------------------------------
__global__ void k_lit(float* __restrict__ rescore_out)
{
    int b    = blockIdx.x;
    int tid  = threadIdx.x;
    int wid  = tid >> 5;
    int lane = tid & 31;
    const float* mo = g_maxout + (size_t)b * DD * HWD;
    const float* q  = g_qmax + b * HWD;

    float part = 0.f;
#pragma unroll 4
    for (int k = 0; k < 128; k++) {
        int p = lane + (k << 5);
        part += q[p] * mo[((p >> 7) << 12) + ((p & 127) << 5) + wid];
    }
#pragma unroll
    for (int off = 16; off; off >>= 1)
        part += __shfl_xor_sync(0xffffffffu, part, off);

    __shared__ float slit[32];
    if (lane == 0) slit[wid] = part * (1.f / 4096.f);
    __syncthreads();

    for (int p = tid; p < HWD; p += 1024) {
        float r = 0.f;
#pragma unroll
        for (int d = 0; d < 32; d++) r += slit[d] * mo[d * HWD + p];
        rescore_out[b * HWD + p] = r;
        g_scale[b * HWD + p] = 1.f + 1.f / (1.f + __expf(-r));
    }
}

// ---------------------------------------------------------------------------
// Kernel W: split K_w into bf16 hi/lo.
// ---------------------------------------------------------------------------
__global__ void k_wconv(const float* __restrict__ W)
{
    int i = blockIdx.x * 256 + threadIdx.x;   // < OC*CIN
    float v = W[i];
    __nv_bfloat16 h = __float2bfloat16(v);
    __nv_bfloat16 l = __float2bfloat16(v - __bfloat162float(h));
    g_Whi[i] = h;
    g_Wlo[i] = l;
}

// ---------------------------------------------------------------------------
// Kernel X: transpose + split shallow: X[b][c][p] fp32 -> Xt[b][p][c] bf16 hi/lo
// ---------------------------------------------------------------------------
__global__ void k_xpose(const float* __restrict__ X)
{
    __shared__ float s[64][65];
    int p0 = blockIdx.x * 64, c0 = blockIdx.y * 64, b = blockIdx.z;
    int tid = threadIdx.x;
    const float* Xb = X + ((size_t)b * CIN + c0) * PIX + p0;

#pragma unroll
    for (int r = 0; r < 16; r++) {
        int c_l = r * 4 + (tid >> 6);
        int p_l = tid & 63;
        s[c_l][p_l] = Xb[(size_t)c_l * PIX + p_l];
    }
    __syncthreads();

    size_t obase = ((size_t)b * PIX + p0) * CIN + c0;
#pragma unroll
    for (int r = 0; r < 8; r++) {
        int idx = tid + r * 256;
        int p_l = idx >> 5;
        int cp  = idx & 31;
        float v0 = s[2 * cp][p_l];
        float v1 = s[2 * cp + 1][p_l];
        __nv_bfloat16 h0 = __float2bfloat16(v0), h1 = __float2bfloat16(v1);
        __nv_bfloat16 l0 = __float2bfloat16(v0 - __bfloat162float(h0));
        __nv_bfloat16 l1 = __float2bfloat16(v1 - __bfloat162float(h1));
        size_t off = obase + (size_t)p_l * CIN + 2 * cp;
        __nv_bfloat162 hp; hp.x = h0; hp.y = h1;
        __nv_bfloat162 lp; lp.x = l0; lp.y = l1;
        *reinterpret_cast<__nv_bfloat162*>(&g_Xhi[off]) = hp;
        *reinterpret_cast<__nv_bfloat162*>(&g_Xlo[off]) = lp;
    }
}

// ---------------------------------------------------------------------------
// Kernel 3: bf16 split GEMM on tensor cores via mma.sync (HMMA).
// C[b][m][n] = sum_c W[m][c] X[b][c][n] + bias[m]  via hi*hi + hi*lo + lo*hi.
// Block 128x128, BK=32, 8 warps (warp tile 64x32), double-buffered cp.async.
// Smem tiles are [row][k] with 40-bf16 (80B) pitch: conflict-free ldmatrix.
// ---------------------------------------------------------------------------
#define GBK   32
#define TPITCH 40                          // bf16 elems per smem row (80B)
#define TB    (128 * TPITCH * 2)           // tile bytes = 10240
#define BUFB  (4 * TB)                     // Ahi,Alo,Bhi,Blo  = 40960
#define GSMEM (2 * BUFB)                   // double buffer    = 81920

__global__ void __launch_bounds__(256)
k_gemm_mma(const float* __restrict__ bias)
{
    extern __shared__ char smem[];
    const uint32_t sbase = smem_u32(smem);
    const int tid  = threadIdx.x;
    const int lane = tid & 31, wid = tid >> 5;
    const int wm = wid & 1;                // m warp coord (0..1) -> 64 rows
    const int wn = wid >> 1;               // n warp coord (0..3) -> 32 cols
    const int n0 = blockIdx.x * 128, m0 = blockIdx.y * 128, b = blockIdx.z;

    const __nv_bfloat16* Ahi = g_Whi + (size_t)m0 * CIN;
    const __nv_bfloat16* Alo = g_Wlo + (size_t)m0 * CIN;
    const __nv_bfloat16* Bhi = g_Xhi + ((size_t)b * PIX + n0) * CIN;
    const __nv_bfloat16* Blo = g_Xlo + ((size_t)b * PIX + n0) * CIN;

    float acc[4][4][4];
#pragma unroll
    for (int i = 0; i < 4; i++)
#pragma unroll
        for (int j = 0; j < 4; j++)
#pragma unroll
            for (int k = 0; k < 4; k++) acc[i][j][k] = 0.f;

    // ---- async tile stage-in: 128 rows x 32 k, 4 x 16B segments per row ----
    auto issue = [&](int c, int buf) {
        int kc = c * GBK;
        uint32_t dbase = sbase + buf * BUFB;
#pragma unroll
        for (int t = 0; t < 2; t++) {
            int s   = tid + t * 256;       // 0..511
            int row = s >> 2, seg = s & 3;
            uint32_t doff = row * (TPITCH * 2) + seg * 16;
            size_t   soff = (size_t)row * CIN + kc + seg * 8;
            cp16(dbase + 0 * TB + doff, Ahi + soff);
            cp16(dbase + 1 * TB + doff, Alo + soff);
            cp16(dbase + 2 * TB + doff, Bhi + soff);
            cp16(dbase + 3 * TB + doff, Blo + soff);
        }
        asm volatile("cp.async.commit_group;" ::: "memory");
    };

    auto compute = [&](int buf) {
        uint32_t base = sbase + buf * BUFB;
        int l16 = lane & 15;
        int kh8 = (lane >> 4) * 8;
#pragma unroll
        for (int ks = 0; ks < 2; ks++) {
            int kb = ks * 16 + kh8;        // k col (elems) for this lane's phase
            uint32_t ahi[4][4], alo[4][4];
#pragma unroll
            for (int i = 0; i < 4; i++) {
                uint32_t off = (uint32_t)((wm * 64 + i * 16 + l16) * (TPITCH * 2) + kb * 2);
                ldsm4(ahi[i], base + 0 * TB + off);
                ldsm4(alo[i], base + 1 * TB + off);
            }
            uint32_t bhi[4][2], blo[4][2];
            {
                uint32_t o0 = (uint32_t)((wn * 32 + l16) * (TPITCH * 2) + kb * 2);
                uint32_t o1 = o0 + 16 * (TPITCH * 2);
                uint32_t t0[4], t1[4];
                ldsm4(t0, base + 2 * TB + o0);
                ldsm4(t1, base + 2 * TB + o1);
                bhi[0][0] = t0[0]; bhi[0][1] = t0[2];
                bhi[1][0] = t0[1]; bhi[1][1] = t0[3];
                bhi[2][0] = t1[0]; bhi[2][1] = t1[2];
                bhi[3][0] = t1[1]; bhi[3][1] = t1[3];
                ldsm4(t0, base + 3 * TB + o0);
                ldsm4(t1, base + 3 * TB + o1);
                blo[0][0] = t0[0]; blo[0][1] = t0[2];
                blo[1][0] = t0[1]; blo[1][1] = t0[3];
                blo[2][0] = t1[0]; blo[2][1] = t1[2];
                blo[3][0] = t1[1]; blo[3][1] = t1[3];
            }
#pragma unroll
            for (int i = 0; i < 4; i++)
#pragma unroll
                for (int j = 0; j < 4; j++) {
                    mma_bf16(acc[i][j], ahi[i], bhi[j]);
                    mma_bf16(acc[i][j], ahi[i], blo[j]);
                    mma_bf16(acc[i][j], alo[i], bhi[j]);
                }
        }
    };

    issue(0, 0);
#pragma unroll 1
    for (int c = 0; c < CIN / GBK; c++) {
        asm volatile("cp.async.wait_group 0;" ::: "memory");
        __syncthreads();
        if (c < CIN / GBK - 1) issue(c + 1, (c + 1) & 1);
        compute(c & 1);
    }

    // ---- epilogue: bias + store fp32 ----
    int r = lane >> 2, cpair = (lane & 3) * 2;
    float* Cb = g_Kx + (size_t)b * OC * PIX;
#pragma unroll
    for (int i = 0; i < 4; i++) {
        int m_g = m0 + wm * 64 + i * 16 + r;
        float b0 = bias[m_g], b1 = bias[m_g + 8];
#pragma unroll
        for (int j = 0; j < 4; j++) {
            int n_g = n0 + wn * 32 + j * 8 + cpair;
            float2 v0 = make_float2(acc[i][j][0] + b0, acc[i][j][1] + b0);
            float2 v1 = make_float2(acc[i][j][2] + b1, acc[i][j][3] + b1);
            *reinterpret_cast<float2*>(Cb + (size_t)m_g * PIX + n_g)       = v0;
            *reinterpret_cast<float2*>(Cb + (size_t)(m_g + 8) * PIX + n_g) = v1;
        }
    }
}

// ---------------------------------------------------------------------------
// Kernel 4: fused unfold(3x3, s2, p1) + softmax attention + gating.
// ---------------------------------------------------------------------------
__global__ void k_att(float* __restrict__ out)
{
    int idx = blockIdx.x * 256 + threadIdx.x;   // < B*OC*HWD
    int p = idx & (HWD - 1);
    int o = (idx >> 12) & (OC - 1);
    int b = idx >> 20;
    int y = p >> 6, x = p & 63;

    const float* base = g_Kx + ((size_t)(b * OC + o) << 14);
    float m  = g_qmean[(b << 12) + p];
    float sc = g_scale[(b << 12) + p];

    float v[9];
    int yy0 = 2 * y - 1, xx0 = 2 * x - 1;
#pragma unroll
    for (int i = 0; i < 3; i++) {
        int yy = yy0 + i;
#pragma unroll
        for (int j = 0; j < 3; j++) {
            int xx = xx0 + j;
            v[i * 3 + j] = (yy >= 0 && xx >= 0) ? base[(yy << 7) + xx] : 0.f;
        }
    }

    float L = m * v[0];
#pragma unroll
    for (int k = 1; k < 9; k++) L = fmaxf(L, m * v[k]);
    float s = 0.f, num = 0.f;
#pragma unroll
    for (int k = 0; k < 9; k++) {
        float e = __expf(m * v[k] - L);
        s   += e;
        num += e * v[k];
    }
    out[idx] = sc * (num / s);
}

// ---------------------------------------------------------------------------
extern "C" void kernel_launch(void* const* d_in, const int* in_sizes, int n_in,
                              void* d_out, int out_size)
{
    const float* shallow = (const float*)d_in[0];
    const float* deep    = (const float*)d_in[1];
    const float* K_w     = (const float*)d_in[2];
    const float* K_b     = (const float*)d_in[3];
    const float* KSA_w   = (const float*)d_in[4];
    const float* KSA_b   = (const float*)d_in[5];
    float* out = (float*)d_out;

    float* rescore_out = out + (size_t)BB * OC * HWD;

    cudaFuncSetAttribute(k_gemm_mma, cudaFuncAttributeMaxDynamicSharedMemorySize,
                         GSMEM);

    k_wconv<<<(OC * CIN) / 256, 256>>>(K_w);
    k_xpose<<<dim3(PIX / 64, CIN / 64, BB), 256>>>(shallow);
    k_maxout<<<dim3(HWD / 128, BB), 128>>>(deep, KSA_w, KSA_b);
    k_lit<<<BB, 1024>>>(rescore_out);
    k_gemm_mma<<<dim3(PIX / 128, OC / 128, BB), 256, GSMEM>>>(K_b);
    k_att<<<(BB * OC * HWD) / 256, 256>>>(out);
}

// round 13
// speedup vs baseline: 1.9921x; 1.2801x over previous
#include <cuda_runtime.h>
#include <cuda_bf16.h>
#include <math.h>
#include <stdint.h>

// Problem constants (fixed by setup_inputs)
#define BB   4
#define C2   512        // deep channels
#define DD   32         // d = 2*C/16
#define HWD  4096       // 64*64 deep spatial
#define OC   256        // out channels of K conv
#define CIN  256        // shallow channels
#define PIX  16384      // 128*128 shallow spatial

// Scratch (device globals: allocation-free)
__device__ float g_maxout[BB * DD * HWD];
__device__ float g_qmax [BB * HWD];
__device__ float g_qmean[BB * HWD];
__device__ float g_scale[BB * HWD];
__device__ float g_lit  [BB * DD];
__device__ float g_Kx[(size_t)BB * OC * PIX];                          // 64MB
__device__ __align__(16) __nv_bfloat16 g_Whi[OC * CIN];
__device__ __align__(16) __nv_bfloat16 g_Wlo[OC * CIN];
__device__ __align__(16) __nv_bfloat16 g_Xhi[(size_t)BB * PIX * CIN];  // [b][p][c]
__device__ __align__(16) __nv_bfloat16 g_Xlo[(size_t)BB * PIX * CIN];

// ---------------------------------------------------------------------------
// PTX helpers (all baseline sm_80+ instructions: family-safe at compute_103)
// ---------------------------------------------------------------------------
__device__ __forceinline__ uint32_t smem_u32(const void* p) {
    uint32_t a;
    asm("{ .reg .u64 t; cvta.to.shared.u64 t, %1; cvt.u32.u64 %0, t; }"
        : "=r"(a) : "l"(p));
    return a;
}
__device__ __forceinline__ void cp16(uint32_t dst, const void* src) {
    asm volatile("cp.async.cg.shared.global [%0], [%1], 16;"
                 :: "r"(dst), "l"(src) : "memory");
}
__device__ __forceinline__ void ldsm4(uint32_t* r, uint32_t addr) {
    asm volatile("ldmatrix.sync.aligned.m8n8.x4.shared.b16 {%0,%1,%2,%3}, [%4];"
                 : "=r"(r[0]), "=r"(r[1]), "=r"(r[2]), "=r"(r[3]) : "r"(addr));
}
__device__ __forceinline__ void mma_bf16(float* c, const uint32_t* a, const uint32_t* b) {
    asm volatile(
        "mma.sync.aligned.m16n8k16.row.col.f32.bf16.bf16.f32 "
        "{%0,%1,%2,%3}, {%4,%5,%6,%7}, {%8,%9}, {%0,%1,%2,%3};"
        : "+f"(c[0]), "+f"(c[1]), "+f"(c[2]), "+f"(c[3])
        : "r"(a[0]), "r"(a[1]), "r"(a[2]), "r"(a[3]), "r"(b[0]), "r"(b[1]));
}

// ---------------------------------------------------------------------------
// Kernel 1: max_out = KSA_w @ deep + KSA_b; q = max_dd; qmean = mean_dd.
// ---------------------------------------------------------------------------
__global__ void k_maxout(const float* __restrict__ deep,
                         const float* __restrict__ ksa_w,
                         const float* __restrict__ ksa_b)
{
    __shared__ float ws[32 * 256];
    int b = blockIdx.y;
    int p = blockIdx.x * 128 + threadIdx.x;

    float acc[32];
#pragma unroll
    for (int d = 0; d < 32; d++) acc[d] = ksa_b[d];

    for (int cc = 0; cc < C2; cc += 256) {
        __syncthreads();
        for (int i = threadIdx.x; i < 32 * 256; i += 128) {
            int d = i >> 8, c = i & 255;
            ws[i] = ksa_w[d * C2 + cc + c];
        }
        __syncthreads();
        const float* dptr = deep + ((size_t)b * C2 + cc) * HWD + p;
#pragma unroll 4
        for (int c = 0; c < 256; c++) {
            float x = dptr[(size_t)c * HWD];
#pragma unroll
            for (int d = 0; d < 32; d++) acc[d] += ws[d * 256 + c] * x;
        }
    }

    float mx = acc[0], sm = 0.f;
#pragma unroll
    for (int d = 0; d < 32; d++) {
        g_maxout[((size_t)b * DD + d) * HWD + p] = acc[d];
        mx = fmaxf(mx, acc[d]);
        sm += acc[d];
    }
    g_qmax [b * HWD + p] = mx;
    g_qmean[b * HWD + p] = sm * (1.f / 32.f);
}

// ---------------------------------------------------------------------------
// Kernel 2a: lit[b][d] = (1/4096) sum_p q[p] * kt[p][d]   (scrambled view).
// One block per (b,d): 128 blocks x 256 threads.
// ---------------------------------------------------------------------------
__global__ void k_lit_a(void)
{
    int d = blockIdx.x & 31;
    int b = blockIdx.x >> 5;
    int tid = threadIdx.x;
    const float* mo = g_maxout + (size_t)b * DD * HWD;
    const float* q  = g_qmax + b * HWD;

    float part = 0.f;
#pragma unroll
    for (int k = 0; k < 16; k++) {
        int p = tid + (k << 8);
        // kt[p][d] = mo_flat[(p>>7)*4096 + ((p&127)<<5) + d]
        part += q[p] * mo[((p >> 7) << 12) + ((p & 127) << 5) + d];
    }
#pragma unroll
    for (int off = 16; off; off >>= 1)
        part += __shfl_xor_sync(0xffffffffu, part, off);

    __shared__ float sred[8];
    if ((tid & 31) == 0) sred[tid >> 5] = part;
    __syncthreads();
    if (tid == 0) {
        float s = 0.f;
#pragma unroll
        for (int w = 0; w < 8; w++) s += sred[w];
        g_lit[blockIdx.x] = s * (1.f / 4096.f);
    }
}

// ---------------------------------------------------------------------------
// Kernel 2b: re_score[b][p] = sum_d lit[b][d] * mo[b][d][p]; scale = 1+sigmoid.
// Grid (HWD/128, B) x 128 threads = full-chip coverage.
// ---------------------------------------------------------------------------
__global__ void k_lit_b(float* __restrict__ rescore_out)
{
    __shared__ float slit[32];
    int b = blockIdx.y;
    int p = blockIdx.x * 128 + threadIdx.x;
    if (threadIdx.x < 32) slit[threadIdx.x] = g_lit[b * DD + threadIdx.x];
    __syncthreads();

    const float* mo = g_maxout + (size_t)b * DD * HWD;
    float r = 0.f;
#pragma unroll
    for (int d = 0; d < 32; d++) r += slit[d] * mo[d * HWD + p];
    rescore_out[b * HWD + p] = r;
    g_scale[b * HWD + p] = 1.f + 1.f / (1.f + __expf(-r));
}

// ---------------------------------------------------------------------------
// Kernel W: split K_w into bf16 hi/lo.
// ---------------------------------------------------------------------------
__global__ void k_wconv(const float* __restrict__ W)
{
    int i = blockIdx.x * 256 + threadIdx.x;   // < OC*CIN
    float v = W[i];
    __nv_bfloat16 h = __float2bfloat16(v);
    __nv_bfloat16 l = __float2bfloat16(v - __bfloat162float(h));
    g_Whi[i] = h;
    g_Wlo[i] = l;
}

// ---------------------------------------------------------------------------
// Kernel X: transpose + split shallow: X[b][c][p] fp32 -> Xt[b][p][c] bf16 hi/lo
// ---------------------------------------------------------------------------
__global__ void k_xpose(const float* __restrict__ X)
{
    __shared__ float s[64][65];
    int p0 = blockIdx.x * 64, c0 = blockIdx.y * 64, b = blockIdx.z;
    int tid = threadIdx.x;
    const float* Xb = X + ((size_t)b * CIN + c0) * PIX + p0;

#pragma unroll
    for (int r = 0; r < 16; r++) {
        int c_l = r * 4 + (tid >> 6);
        int p_l = tid & 63;
        s[c_l][p_l] = Xb[(size_t)c_l * PIX + p_l];
    }
    __syncthreads();

    size_t obase = ((size_t)b * PIX + p0) * CIN + c0;
#pragma unroll
    for (int r = 0; r < 8; r++) {
        int idx = tid + r * 256;
        int p_l = idx >> 5;
        int cp  = idx & 31;
        float v0 = s[2 * cp][p_l];
        float v1 = s[2 * cp + 1][p_l];
        __nv_bfloat16 h0 = __float2bfloat16(v0), h1 = __float2bfloat16(v1);
        __nv_bfloat16 l0 = __float2bfloat16(v0 - __bfloat162float(h0));
        __nv_bfloat16 l1 = __float2bfloat16(v1 - __bfloat162float(h1));
        size_t off = obase + (size_t)p_l * CIN + 2 * cp;
        __nv_bfloat162 hp; hp.x = h0; hp.y = h1;
        __nv_bfloat162 lp; lp.x = l0; lp.y = l1;
        *reinterpret_cast<__nv_bfloat162*>(&g_Xhi[off]) = hp;
        *reinterpret_cast<__nv_bfloat162*>(&g_Xlo[off]) = lp;
    }
}

// ---------------------------------------------------------------------------
// Kernel 3: bf16 split GEMM on tensor cores via mma.sync (HMMA).
// Block 128x128, BK=32, 8 warps (warp tile 64x32), double-buffered cp.async.
// ---------------------------------------------------------------------------
#define GBK   32
#define TPITCH 40                          // bf16 elems per smem row (80B)
#define TB    (128 * TPITCH * 2)           // tile bytes = 10240
#define BUFB  (4 * TB)                     // Ahi,Alo,Bhi,Blo  = 40960
#define GSMEM (2 * BUFB)                   // double buffer    = 81920

__global__ void __launch_bounds__(256)
k_gemm_mma(const float* __restrict__ bias)
{
    extern __shared__ char smem[];
    const uint32_t sbase = smem_u32(smem);
    const int tid  = threadIdx.x;
    const int lane = tid & 31, wid = tid >> 5;
    const int wm = wid & 1;                // m warp coord (0..1) -> 64 rows
    const int wn = wid >> 1;               // n warp coord (0..3) -> 32 cols
    const int n0 = blockIdx.x * 128, m0 = blockIdx.y * 128, b = blockIdx.z;

    const __nv_bfloat16* Ahi = g_Whi + (size_t)m0 * CIN;
    const __nv_bfloat16* Alo = g_Wlo + (size_t)m0 * CIN;
    const __nv_bfloat16* Bhi = g_Xhi + ((size_t)b * PIX + n0) * CIN;
    const __nv_bfloat16* Blo = g_Xlo + ((size_t)b * PIX + n0) * CIN;

    float acc[4][4][4];
#pragma unroll
    for (int i = 0; i < 4; i++)
#pragma unroll
        for (int j = 0; j < 4; j++)
#pragma unroll
            for (int k = 0; k < 4; k++) acc[i][j][k] = 0.f;

    auto issue = [&](int c, int buf) {
        int kc = c * GBK;
        uint32_t dbase = sbase + buf * BUFB;
#pragma unroll
        for (int t = 0; t < 2; t++) {
            int s   = tid + t * 256;       // 0..511
            int row = s >> 2, seg = s & 3;
            uint32_t doff = row * (TPITCH * 2) + seg * 16;
            size_t   soff = (size_t)row * CIN + kc + seg * 8;
            cp16(dbase + 0 * TB + doff, Ahi + soff);
            cp16(dbase + 1 * TB + doff, Alo + soff);
            cp16(dbase + 2 * TB + doff, Bhi + soff);
            cp16(dbase + 3 * TB + doff, Blo + soff);
        }
        asm volatile("cp.async.commit_group;" ::: "memory");
    };

    auto compute = [&](int buf) {
        uint32_t base = sbase + buf * BUFB;
        int l16 = lane & 15;
        int kh8 = (lane >> 4) * 8;
#pragma unroll
        for (int ks = 0; ks < 2; ks++) {
            int kb = ks * 16 + kh8;
            uint32_t ahi[4][4], alo[4][4];
#pragma unroll
            for (int i = 0; i < 4; i++) {
                uint32_t off = (uint32_t)((wm * 64 + i * 16 + l16) * (TPITCH * 2) + kb * 2);
                ldsm4(ahi[i], base + 0 * TB + off);
                ldsm4(alo[i], base + 1 * TB + off);
            }
            uint32_t bhi[4][2], blo[4][2];
            {
                uint32_t o0 = (uint32_t)((wn * 32 + l16) * (TPITCH * 2) + kb * 2);
                uint32_t o1 = o0 + 16 * (TPITCH * 2);
                uint32_t t0[4], t1[4];
                ldsm4(t0, base + 2 * TB + o0);
                ldsm4(t1, base + 2 * TB + o1);
                bhi[0][0] = t0[0]; bhi[0][1] = t0[2];
                bhi[1][0] = t0[1]; bhi[1][1] = t0[3];
                bhi[2][0] = t1[0]; bhi[2][1] = t1[2];
                bhi[3][0] = t1[1]; bhi[3][1] = t1[3];
                ldsm4(t0, base + 3 * TB + o0);
                ldsm4(t1, base + 3 * TB + o1);
                blo[0][0] = t0[0]; blo[0][1] = t0[2];
                blo[1][0] = t0[1]; blo[1][1] = t0[3];
                blo[2][0] = t1[0]; blo[2][1] = t1[2];
                blo[3][0] = t1[1]; blo[3][1] = t1[3];
            }
#pragma unroll
            for (int i = 0; i < 4; i++)
#pragma unroll
                for (int j = 0; j < 4; j++) {
                    mma_bf16(acc[i][j], ahi[i], bhi[j]);
                    mma_bf16(acc[i][j], ahi[i], blo[j]);
                    mma_bf16(acc[i][j], alo[i], bhi[j]);
                }
        }
    };

    issue(0, 0);
#pragma unroll 1
    for (int c = 0; c < CIN / GBK; c++) {
        asm volatile("cp.async.wait_group 0;" ::: "memory");
        __syncthreads();
        if (c < CIN / GBK - 1) issue(c + 1, (c + 1) & 1);
        compute(c & 1);
    }

    // ---- epilogue: bias + store fp32 ----
    int r = lane >> 2, cpair = (lane & 3) * 2;
    float* Cb = g_Kx + (size_t)b * OC * PIX;
#pragma unroll
    for (int i = 0; i < 4; i++) {
        int m_g = m0 + wm * 64 + i * 16 + r;
        float b0 = bias[m_g], b1 = bias[m_g + 8];
#pragma unroll
        for (int j = 0; j < 4; j++) {
            int n_g = n0 + wn * 32 + j * 8 + cpair;
            float2 v0 = make_float2(acc[i][j][0] + b0, acc[i][j][1] + b0);
            float2 v1 = make_float2(acc[i][j][2] + b1, acc[i][j][3] + b1);
            *reinterpret_cast<float2*>(Cb + (size_t)m_g * PIX + n_g)       = v0;
            *reinterpret_cast<float2*>(Cb + (size_t)(m_g + 8) * PIX + n_g) = v1;
        }
    }
}

// ---------------------------------------------------------------------------
// Kernel 4: fused unfold(3x3, s2, p1) + softmax attention + gating.
// ---------------------------------------------------------------------------
__global__ void k_att(float* __restrict__ out)
{
    int idx = blockIdx.x * 256 + threadIdx.x;   // < B*OC*HWD
    int p = idx & (HWD - 1);
    int o = (idx >> 12) & (OC - 1);
    int b = idx >> 20;
    int y = p >> 6, x = p & 63;

    const float* base = g_Kx + ((size_t)(b * OC + o) << 14);
    float m  = g_qmean[(b << 12) + p];
    float sc = g_scale[(b << 12) + p];

    float v[9];
    int yy0 = 2 * y - 1, xx0 = 2 * x - 1;
#pragma unroll
    for (int i = 0; i < 3; i++) {
        int yy = yy0 + i;
#pragma unroll
        for (int j = 0; j < 3; j++) {
            int xx = xx0 + j;
            v[i * 3 + j] = (yy >= 0 && xx >= 0) ? base[(yy << 7) + xx] : 0.f;
        }
    }

    float L = m * v[0];
#pragma unroll
    for (int k = 1; k < 9; k++) L = fmaxf(L, m * v[k]);
    float s = 0.f, num = 0.f;
#pragma unroll
    for (int k = 0; k < 9; k++) {
        float e = __expf(m * v[k] - L);
        s   += e;
        num += e * v[k];
    }
    out[idx] = sc * (num / s);
}

// ---------------------------------------------------------------------------
extern "C" void kernel_launch(void* const* d_in, const int* in_sizes, int n_in,
                              void* d_out, int out_size)
{
    const float* shallow = (const float*)d_in[0];
    const float* deep    = (const float*)d_in[1];
    const float* K_w     = (const float*)d_in[2];
    const float* K_b     = (const float*)d_in[3];
    const float* KSA_w   = (const float*)d_in[4];
    const float* KSA_b   = (const float*)d_in[5];
    float* out = (float*)d_out;

    float* rescore_out = out + (size_t)BB * OC * HWD;

    cudaFuncSetAttribute(k_gemm_mma, cudaFuncAttributeMaxDynamicSharedMemorySize,
                         GSMEM);

    k_wconv<<<(OC * CIN) / 256, 256>>>(K_w);
    k_xpose<<<dim3(PIX / 64, CIN / 64, BB), 256>>>(shallow);
    k_maxout<<<dim3(HWD / 128, BB), 128>>>(deep, KSA_w, KSA_b);
    k_lit_a<<<BB * DD, 256>>>();
    k_lit_b<<<dim3(HWD / 128, BB), 128>>>(rescore_out);
    k_gemm_mma<<<dim3(PIX / 128, OC / 128, BB), 256, GSMEM>>>(K_b);
    k_att<<<(BB * OC * HWD) / 256, 256>>>(out);
}

// round 14
// speedup vs baseline: 2.5986x; 1.3045x over previous
#include <cuda_runtime.h>
#include <cuda_bf16.h>
#include <math.h>
#include <stdint.h>

// Problem constants (fixed by setup_inputs)
#define BB   4
#define C2   512        // deep channels
#define DD   32         // d = 2*C/16
#define HWD  4096       // 64*64 deep spatial
#define OC   256        // out channels of K conv
#define CIN  256        // shallow channels
#define PIX  16384      // 128*128 shallow spatial

typedef unsigned long long ull;

// Scratch (device globals: allocation-free)
__device__ float g_maxout[BB * DD * HWD];
__device__ float g_mpart[4][BB * DD * HWD];                            // split-K partials, 8MB
__device__ float g_qmax [BB * HWD];
__device__ float g_qmean[BB * HWD];
__device__ float g_scale[BB * HWD];
__device__ float g_litpart[BB * DD * 4];
__device__ float g_Kx[(size_t)BB * OC * PIX];                          // 64MB
__device__ __align__(16) __nv_bfloat16 g_Whi[OC * CIN];
__device__ __align__(16) __nv_bfloat16 g_Wlo[OC * CIN];
__device__ __align__(16) __nv_bfloat16 g_Xhi[(size_t)BB * CIN * PIX];  // [b][c][p] (native layout)
__device__ __align__(16) __nv_bfloat16 g_Xlo[(size_t)BB * CIN * PIX];

// ---------------------------------------------------------------------------
// PTX helpers (baseline sm_80+/family-safe; fma.rn.f32x2 verified in R8)
// ---------------------------------------------------------------------------
__device__ __forceinline__ uint32_t smem_u32(const void* p) {
    uint32_t a;
    asm("{ .reg .u64 t; cvta.to.shared.u64 t, %1; cvt.u32.u64 %0, t; }"
        : "=r"(a) : "l"(p));
    return a;
}
__device__ __forceinline__ void cp16(uint32_t dst, const void* src) {
    asm volatile("cp.async.cg.shared.global [%0], [%1], 16;"
                 :: "r"(dst), "l"(src) : "memory");
}
__device__ __forceinline__ void ldsm4(uint32_t* r, uint32_t addr) {
    asm volatile("ldmatrix.sync.aligned.m8n8.x4.shared.b16 {%0,%1,%2,%3}, [%4];"
                 : "=r"(r[0]), "=r"(r[1]), "=r"(r[2]), "=r"(r[3]) : "r"(addr));
}
__device__ __forceinline__ void ldsm4t(uint32_t* r, uint32_t addr) {
    asm volatile("ldmatrix.sync.aligned.m8n8.x4.trans.shared.b16 {%0,%1,%2,%3}, [%4];"
                 : "=r"(r[0]), "=r"(r[1]), "=r"(r[2]), "=r"(r[3]) : "r"(addr));
}
__device__ __forceinline__ void mma_bf16(float* c, const uint32_t* a, const uint32_t* b) {
    asm volatile(
        "mma.sync.aligned.m16n8k16.row.col.f32.bf16.bf16.f32 "
        "{%0,%1,%2,%3}, {%4,%5,%6,%7}, {%8,%9}, {%0,%1,%2,%3};"
        : "+f"(c[0]), "+f"(c[1]), "+f"(c[2]), "+f"(c[3])
        : "r"(a[0]), "r"(a[1]), "r"(a[2]), "r"(a[3]), "r"(b[0]), "r"(b[1]));
}
__device__ __forceinline__ void ffma2(ull& d, ull a, ull b) {
    asm("fma.rn.f32x2 %0, %1, %2, %0;" : "+l"(d) : "l"(a), "l"(b));
}
__device__ __forceinline__ ull packf2(float lo, float hi) {
    ull v; asm("mov.b64 %0, {%1, %2};" : "=l"(v) : "f"(lo), "f"(hi)); return v;
}
__device__ __forceinline__ void unpackf2(float& lo, float& hi, ull v) {
    asm("mov.b64 {%0, %1}, %2;" : "=f"(lo), "=f"(hi) : "l"(v));
}

// ---------------------------------------------------------------------------
// Kernel 1a: partial max_out over a 128-channel chunk (split-K x4).
// Block: 128 threads = 2 d-halves x 64 px-quads (256 px per block).
// Weights dup-packed (w,w) in smem for FFMA2; per c: 16 LDS.64 + 32 FFMA2.
// ---------------------------------------------------------------------------
__global__ void __launch_bounds__(128)
k_maxout_part(const float* __restrict__ deep, const float* __restrict__ ksa_w)
{
    __shared__ ull ws2[32 * 128];   // 32KB, dup-packed
    int b = blockIdx.y, chunk = blockIdx.z;
    int tid = threadIdx.x;
    int dh = tid & 1;               // d half: 0 -> d 0..15, 1 -> d 16..31
    int pq = tid >> 1;              // pixel quad index 0..63
    int px = blockIdx.x * 256 + pq * 4;

    for (int i = tid; i < 32 * 128; i += 128) {
        int d = i >> 7, c = i & 127;
        float w = ksa_w[d * C2 + chunk * 128 + c];
        ws2[i] = packf2(w, w);
    }
    __syncthreads();

    ull acc0[16], acc1[16];
#pragma unroll
    for (int d = 0; d < 16; d++) { acc0[d] = 0ull; acc1[d] = 0ull; }

    const float* dp = deep + ((size_t)b * C2 + chunk * 128) * HWD + px;
    const ull* wrow = ws2 + (dh * 16) * 128;
#pragma unroll 2
    for (int c = 0; c < 128; c++) {
        float4 x = *reinterpret_cast<const float4*>(dp + (size_t)c * HWD);
        ull xp0 = packf2(x.x, x.y);
        ull xp1 = packf2(x.z, x.w);
#pragma unroll
        for (int d = 0; d < 16; d++) {
            ull w = wrow[d * 128 + c];
            ffma2(acc0[d], w, xp0);
            ffma2(acc1[d], w, xp1);
        }
    }

    float* op = g_mpart[chunk] + ((size_t)b * DD + dh * 16) * HWD + px;
#pragma unroll
    for (int d = 0; d < 16; d++) {
        float a, bb_, c, dd_;
        unpackf2(a, bb_, acc0[d]);
        unpackf2(c, dd_, acc1[d]);
        *reinterpret_cast<float2*>(op + (size_t)d * HWD)     = make_float2(a, bb_);
        *reinterpret_cast<float2*>(op + (size_t)d * HWD + 2) = make_float2(c, dd_);
    }
}

// ---------------------------------------------------------------------------
// Kernel 1b: combine partials -> maxout, qmax, qmean.
// ---------------------------------------------------------------------------
__global__ void k_maxcomb(const float* __restrict__ ksa_b)
{
    __shared__ float sb[32];
    int b = blockIdx.y;
    int p = blockIdx.x * 128 + threadIdx.x;
    if (threadIdx.x < 32) sb[threadIdx.x] = ksa_b[threadIdx.x];
    __syncthreads();

    float mx = -1e30f, sm = 0.f;
#pragma unroll
    for (int d = 0; d < 32; d++) {
        size_t off = ((size_t)b * DD + d) * HWD + p;
        float v = sb[d] + g_mpart[0][off] + g_mpart[1][off]
                        + g_mpart[2][off] + g_mpart[3][off];
        g_maxout[off] = v;
        mx = fmaxf(mx, v);
        sm += v;
    }
    g_qmax [b * HWD + p] = mx;
    g_qmean[b * HWD + p] = sm * (1.f / 32.f);
}

// ---------------------------------------------------------------------------
// Kernel 2a: lit partials. 512 blocks: (b,d) x 4 pixel chunks.
// kt[p][d] = mo_flat[(p>>7)*4096 + ((p&127)<<5) + d]  (scrambled flat view)
// ---------------------------------------------------------------------------
__global__ void k_lit_a(void)
{
    int chunk = blockIdx.x & 3;
    int bd = blockIdx.x >> 2;
    int d = bd & 31, b = bd >> 5;
    int tid = threadIdx.x;
    const float* mo = g_maxout + (size_t)b * DD * HWD;
    const float* q  = g_qmax + b * HWD;

    float part = 0.f;
#pragma unroll
    for (int k = 0; k < 4; k++) {
        int p = chunk * 1024 + tid + (k << 8);
        part += q[p] * mo[((p >> 7) << 12) + ((p & 127) << 5) + d];
    }
#pragma unroll
    for (int off = 16; off; off >>= 1)
        part += __shfl_xor_sync(0xffffffffu, part, off);

    __shared__ float sred[8];
    if ((tid & 31) == 0) sred[tid >> 5] = part;
    __syncthreads();
    if (tid == 0) {
        float s = 0.f;
#pragma unroll
        for (int w = 0; w < 8; w++) s += sred[w];
        g_litpart[blockIdx.x] = s;
    }
}

// ---------------------------------------------------------------------------
// Kernel 2b: re_score = sum_d lit[d]*mo[d][p]; scale = 1 + sigmoid.
// ---------------------------------------------------------------------------
__global__ void k_lit_b(float* __restrict__ rescore_out)
{
    __shared__ float slit[32];
    int b = blockIdx.y;
    int p = blockIdx.x * 128 + threadIdx.x;
    if (threadIdx.x < 32) {
        const float* lp = g_litpart + (b * DD + threadIdx.x) * 4;
        slit[threadIdx.x] = (lp[0] + lp[1] + lp[2] + lp[3]) * (1.f / 4096.f);
    }
    __syncthreads();

    const float* mo = g_maxout + (size_t)b * DD * HWD;
    float r = 0.f;
#pragma unroll
    for (int d = 0; d < 32; d++) r += slit[d] * mo[d * HWD + p];
    rescore_out[b * HWD + p] = r;
    g_scale[b * HWD + p] = 1.f + 1.f / (1.f + __expf(-r));
}

// ---------------------------------------------------------------------------
// Kernel W: split K_w into bf16 hi/lo.
// ---------------------------------------------------------------------------
__global__ void k_wconv(const float* __restrict__ W)
{
    int i = blockIdx.x * 256 + threadIdx.x;   // < OC*CIN
    float v = W[i];
    __nv_bfloat16 h = __float2bfloat16(v);
    __nv_bfloat16 l = __float2bfloat16(v - __bfloat162float(h));
    g_Whi[i] = h;
    g_Wlo[i] = l;
}

// ---------------------------------------------------------------------------
// Kernel X: elementwise split (NO transpose; keep native [b][c][p] layout).
// 8 elems per thread: read 2x float4, write uint4 hi + uint4 lo.
// ---------------------------------------------------------------------------
__device__ __forceinline__ uint32_t bfpk(__nv_bfloat16 a, __nv_bfloat16 b) {
    __nv_bfloat162 t; t.x = a; t.y = b;
    return *reinterpret_cast<uint32_t*>(&t);
}
__global__ void k_xsplit(const float* __restrict__ X)
{
    size_t i = ((size_t)blockIdx.x * 256 + threadIdx.x) * 8;
    float4 a = *reinterpret_cast<const float4*>(X + i);
    float4 b = *reinterpret_cast<const float4*>(X + i + 4);
    float v[8] = {a.x, a.y, a.z, a.w, b.x, b.y, b.z, b.w};
    __nv_bfloat16 h[8], l[8];
#pragma unroll
    for (int k = 0; k < 8; k++) {
        h[k] = __float2bfloat16(v[k]);
        l[k] = __float2bfloat16(v[k] - __bfloat162float(h[k]));
    }
    uint4 hv = make_uint4(bfpk(h[0], h[1]), bfpk(h[2], h[3]),
                          bfpk(h[4], h[5]), bfpk(h[6], h[7]));
    uint4 lv = make_uint4(bfpk(l[0], l[1]), bfpk(l[2], l[3]),
                          bfpk(l[4], l[5]), bfpk(l[6], l[7]));
    *reinterpret_cast<uint4*>(g_Xhi + i) = hv;
    *reinterpret_cast<uint4*>(g_Xlo + i) = lv;
}

// ---------------------------------------------------------------------------
// Kernel 3: bf16 split GEMM via mma.sync (HMMA), hi*hi + hi*lo + lo*hi.
// Block 128x128, BK=32, 8 warps (64x32 each), double-buffered cp.async.
// A tiles [m][k] pitch-80B (conflict-free non-trans ldmatrix).
// B tiles [k][n] 256B rows, seg-XOR swizzle, ldmatrix.x4.trans fragments
// -> consumes X's native [c][p] layout (no global transpose needed).
// ---------------------------------------------------------------------------
#define GBK  32
#define ATB  (128 * 80)               // 10240 per A tile
#define BTB  (32 * 256)               // 8192  per B tile
#define BUFB (2 * ATB + 2 * BTB)      // 36864
#define GSMEM (2 * BUFB)              // 73728

__global__ void __launch_bounds__(256)
k_gemm_mma(const float* __restrict__ bias)
{
    extern __shared__ char smem[];
    const uint32_t sbase = smem_u32(smem);
    const int tid  = threadIdx.x;
    const int lane = tid & 31, wid = tid >> 5;
    const int wm = wid & 1;                // m warp coord -> 64 rows
    const int wn = wid >> 1;               // n warp coord -> 32 cols
    const int n0 = blockIdx.x * 128, m0 = blockIdx.y * 128, b = blockIdx.z;

    const __nv_bfloat16* Ahi = g_Whi + (size_t)m0 * CIN;
    const __nv_bfloat16* Alo = g_Wlo + (size_t)m0 * CIN;
    const __nv_bfloat16* Bhi = g_Xhi + (size_t)b * CIN * PIX + n0;
    const __nv_bfloat16* Blo = g_Xlo + (size_t)b * CIN * PIX + n0;

    float acc[4][4][4];
#pragma unroll
    for (int i = 0; i < 4; i++)
#pragma unroll
        for (int j = 0; j < 4; j++)
#pragma unroll
            for (int k = 0; k < 4; k++) acc[i][j][k] = 0.f;

    auto issue = [&](int cidx, int buf) {
        int kc = cidx * GBK;
        uint32_t dbase = sbase + buf * BUFB;
#pragma unroll
        for (int t = 0; t < 2; t++) {
            int s = tid + t * 256;
            {   // A tiles: 128 rows x 4 segs of 16B (64B data in 80B pitch)
                int row = s >> 2, seg = s & 3;
                uint32_t doff = row * 80 + seg * 16;
                size_t   soff = (size_t)row * CIN + kc + seg * 8;
                cp16(dbase + doff,       Ahi + soff);
                cp16(dbase + ATB + doff, Alo + soff);
            }
            {   // B tiles: 32 k-rows x 16 segs of 16B, seg-XOR swizzle
                int row = s >> 4, seg = s & 15;
                uint32_t doff = row * 256 + ((seg ^ (row & 7)) << 4);
                size_t   soff = (size_t)(kc + row) * PIX + seg * 8;
                cp16(dbase + 2 * ATB + doff,       Bhi + soff);
                cp16(dbase + 2 * ATB + BTB + doff, Blo + soff);
            }
        }
        asm volatile("cp.async.commit_group;" ::: "memory");
    };

    auto compute = [&](int buf) {
        uint32_t base = sbase + buf * BUFB;
        int l16 = lane & 15;
        int kh8 = (lane >> 4) * 8;
        int krow_base = (lane & 7) + ((lane & 16) >> 1);
        int ncol_base = wn * 32 + (lane & 8);
#pragma unroll
        for (int ks = 0; ks < 2; ks++) {
            int kb = ks * 16 + kh8;
            uint32_t ahi[4][4], alo[4][4];
#pragma unroll
            for (int i = 0; i < 4; i++) {
                uint32_t off = (uint32_t)((wm * 64 + i * 16 + l16) * 80 + kb * 2);
                ldsm4(ahi[i], base + off);
                ldsm4(alo[i], base + ATB + off);
            }
            uint32_t bhi[4][2], blo[4][2];
            {
                int krow = ks * 16 + krow_base;
                uint32_t brow = base + 2 * ATB + krow * 256;
                uint32_t sw = (uint32_t)((krow & 7) << 4);
#pragma unroll
                for (int jj = 0; jj < 2; jj++) {
                    uint32_t boff = ((uint32_t)((ncol_base + jj * 16) * 2)) ^ sw;
                    uint32_t t0[4], t1[4];
                    ldsm4t(t0, brow + boff);
                    ldsm4t(t1, brow + BTB + boff);
                    bhi[jj * 2][0]     = t0[0]; bhi[jj * 2 + 1][0] = t0[1];
                    bhi[jj * 2][1]     = t0[2]; bhi[jj * 2 + 1][1] = t0[3];
                    blo[jj * 2][0]     = t1[0]; blo[jj * 2 + 1][0] = t1[1];
                    blo[jj * 2][1]     = t1[2]; blo[jj * 2 + 1][1] = t1[3];
                }
            }
#pragma unroll
            for (int i = 0; i < 4; i++)
#pragma unroll
                for (int j = 0; j < 4; j++) {
                    mma_bf16(acc[i][j], ahi[i], bhi[j]);
                    mma_bf16(acc[i][j], ahi[i], blo[j]);
                    mma_bf16(acc[i][j], alo[i], bhi[j]);
                }
        }
    };

    issue(0, 0);
#pragma unroll 1
    for (int c = 0; c < CIN / GBK; c++) {
        asm volatile("cp.async.wait_group 0;" ::: "memory");
        __syncthreads();
        if (c < CIN / GBK - 1) issue(c + 1, (c + 1) & 1);
        compute(c & 1);
    }

    // ---- epilogue: bias + store fp32 ----
    int r = lane >> 2, cpair = (lane & 3) * 2;
    float* Cb = g_Kx + (size_t)b * OC * PIX;
#pragma unroll
    for (int i = 0; i < 4; i++) {
        int m_g = m0 + wm * 64 + i * 16 + r;
        float b0 = bias[m_g], b1 = bias[m_g + 8];
#pragma unroll
        for (int j = 0; j < 4; j++) {
            int n_g = n0 + wn * 32 + j * 8 + cpair;
            float2 v0 = make_float2(acc[i][j][0] + b0, acc[i][j][1] + b0);
            float2 v1 = make_float2(acc[i][j][2] + b1, acc[i][j][3] + b1);
            *reinterpret_cast<float2*>(Cb + (size_t)m_g * PIX + n_g)       = v0;
            *reinterpret_cast<float2*>(Cb + (size_t)(m_g + 8) * PIX + n_g) = v1;
        }
    }
}

// ---------------------------------------------------------------------------
// Kernel 4: fused unfold(3x3, s2, p1) + softmax attention + gating.
// ---------------------------------------------------------------------------
__global__ void k_att(float* __restrict__ out)
{
    int idx = blockIdx.x * 256 + threadIdx.x;   // < B*OC*HWD
    int p = idx & (HWD - 1);
    int o = (idx >> 12) & (OC - 1);
    int b = idx >> 20;
    int y = p >> 6, x = p & 63;

    const float* base = g_Kx + ((size_t)(b * OC + o) << 14);
    float m  = g_qmean[(b << 12) + p];
    float sc = g_scale[(b << 12) + p];

    float v[9];
    int yy0 = 2 * y - 1, xx0 = 2 * x - 1;
#pragma unroll
    for (int i = 0; i < 3; i++) {
        int yy = yy0 + i;
#pragma unroll
        for (int j = 0; j < 3; j++) {
            int xx = xx0 + j;
            v[i * 3 + j] = (yy >= 0 && xx >= 0) ? base[(yy << 7) + xx] : 0.f;
        }
    }

    float L = m * v[0];
#pragma unroll
    for (int k = 1; k < 9; k++) L = fmaxf(L, m * v[k]);
    float s = 0.f, num = 0.f;
#pragma unroll
    for (int k = 0; k < 9; k++) {
        float e = __expf(m * v[k] - L);
        s   += e;
        num += e * v[k];
    }
    out[idx] = sc * __fdividef(num, s);
}

// ---------------------------------------------------------------------------
extern "C" void kernel_launch(void* const* d_in, const int* in_sizes, int n_in,
                              void* d_out, int out_size)
{
    const float* shallow = (const float*)d_in[0];
    const float* deep    = (const float*)d_in[1];
    const float* K_w     = (const float*)d_in[2];
    const float* K_b     = (const float*)d_in[3];
    const float* KSA_w   = (const float*)d_in[4];
    const float* KSA_b   = (const float*)d_in[5];
    float* out = (float*)d_out;

    float* rescore_out = out + (size_t)BB * OC * HWD;

    cudaFuncSetAttribute(k_gemm_mma, cudaFuncAttributeMaxDynamicSharedMemorySize,
                         GSMEM);

    k_wconv<<<(OC * CIN) / 256, 256>>>(K_w);
    k_xsplit<<<(int)(((size_t)BB * CIN * PIX) / (256 * 8)), 256>>>(shallow);
    k_maxout_part<<<dim3(HWD / 256, BB, 4), 128>>>(deep, KSA_w);
    k_maxcomb<<<dim3(HWD / 128, BB), 128>>>(KSA_b);
    k_lit_a<<<BB * DD * 4, 256>>>();
    k_lit_b<<<dim3(HWD / 128, BB), 128>>>(rescore_out);
    k_gemm_mma<<<dim3(PIX / 128, OC / 128, BB), 256, GSMEM>>>(K_b);
    k_att<<<(BB * OC * HWD) / 256, 256>>>(out);
}

// round 15
// speedup vs baseline: 2.6393x; 1.0157x over previous
#include <cuda_runtime.h>
#include <cuda_bf16.h>
#include <math.h>
#include <stdint.h>

// Problem constants (fixed by setup_inputs)
#define BB   4
#define C2   512        // deep channels
#define DD   32         // d = 2*C/16
#define HWD  4096       // 64*64 deep spatial
#define OC   256        // out channels of K conv
#define CIN  256        // shallow channels
#define PIX  16384      // 128*128 shallow spatial

typedef unsigned long long ull;

// Scratch (device globals: allocation-free)
__device__ float g_maxout[BB * DD * HWD];
__device__ float g_mpart[4][BB * DD * HWD];                            // split-K partials
__device__ float g_qmax [BB * HWD];
__device__ float g_qmean[BB * HWD];
__device__ float g_scale[BB * HWD];
__device__ float g_litpart[BB * DD * 4];
__device__ float g_Kx[(size_t)BB * OC * PIX];                          // 64MB
__device__ __align__(16) __nv_bfloat16 g_Whi[OC * CIN];
__device__ __align__(16) __nv_bfloat16 g_Wlo[OC * CIN];
__device__ __align__(16) __nv_bfloat16 g_Xhi[(size_t)BB * CIN * PIX];  // [b][c][p]
__device__ __align__(16) __nv_bfloat16 g_Xlo[(size_t)BB * CIN * PIX];

// ---------------------------------------------------------------------------
// PTX helpers
// ---------------------------------------------------------------------------
__device__ __forceinline__ uint32_t smem_u32(const void* p) {
    uint32_t a;
    asm("{ .reg .u64 t; cvta.to.shared.u64 t, %1; cvt.u32.u64 %0, t; }"
        : "=r"(a) : "l"(p));
    return a;
}
__device__ __forceinline__ void cp16(uint32_t dst, const void* src) {
    asm volatile("cp.async.cg.shared.global [%0], [%1], 16;"
                 :: "r"(dst), "l"(src) : "memory");
}
__device__ __forceinline__ void ldsm4(uint32_t* r, uint32_t addr) {
    asm volatile("ldmatrix.sync.aligned.m8n8.x4.shared.b16 {%0,%1,%2,%3}, [%4];"
                 : "=r"(r[0]), "=r"(r[1]), "=r"(r[2]), "=r"(r[3]) : "r"(addr));
}
__device__ __forceinline__ void ldsm4t(uint32_t* r, uint32_t addr) {
    asm volatile("ldmatrix.sync.aligned.m8n8.x4.trans.shared.b16 {%0,%1,%2,%3}, [%4];"
                 : "=r"(r[0]), "=r"(r[1]), "=r"(r[2]), "=r"(r[3]) : "r"(addr));
}
__device__ __forceinline__ void mma_bf16(float* c, const uint32_t* a, const uint32_t* b) {
    asm volatile(
        "mma.sync.aligned.m16n8k16.row.col.f32.bf16.bf16.f32 "
        "{%0,%1,%2,%3}, {%4,%5,%6,%7}, {%8,%9}, {%0,%1,%2,%3};"
        : "+f"(c[0]), "+f"(c[1]), "+f"(c[2]), "+f"(c[3])
        : "r"(a[0]), "r"(a[1]), "r"(a[2]), "r"(a[3]), "r"(b[0]), "r"(b[1]));
}
__device__ __forceinline__ void ffma2(ull& d, ull a, ull b) {
    asm("fma.rn.f32x2 %0, %1, %2, %0;" : "+l"(d) : "l"(a), "l"(b));
}
__device__ __forceinline__ ull packf2(float lo, float hi) {
    ull v; asm("mov.b64 %0, {%1, %2};" : "=l"(v) : "f"(lo), "f"(hi)); return v;
}
__device__ __forceinline__ void unpackf2(float& lo, float& hi, ull v) {
    asm("mov.b64 {%0, %1}, %2;" : "=f"(lo), "=f"(hi) : "l"(v));
}

// ---------------------------------------------------------------------------
// Kernel 1a: partial max_out over a 128-channel chunk (split-K x4), FFMA2.
// ---------------------------------------------------------------------------
__global__ void __launch_bounds__(128)
k_maxout_part(const float* __restrict__ deep, const float* __restrict__ ksa_w)
{
    __shared__ ull ws2[32 * 128];   // 32KB, dup-packed (w,w)
    int b = blockIdx.y, chunk = blockIdx.z;
    int tid = threadIdx.x;
    int dh = tid & 1;               // d half
    int pq = tid >> 1;              // pixel quad 0..63
    int px = blockIdx.x * 256 + pq * 4;

    for (int i = tid; i < 32 * 128; i += 128) {
        int d = i >> 7, c = i & 127;
        float w = ksa_w[d * C2 + chunk * 128 + c];
        ws2[i] = packf2(w, w);
    }
    __syncthreads();

    ull acc0[16], acc1[16];
#pragma unroll
    for (int d = 0; d < 16; d++) { acc0[d] = 0ull; acc1[d] = 0ull; }

    const float* dp = deep + ((size_t)b * C2 + chunk * 128) * HWD + px;
    const ull* wrow = ws2 + (dh * 16) * 128;
#pragma unroll 2
    for (int c = 0; c < 128; c++) {
        float4 x = *reinterpret_cast<const float4*>(dp + (size_t)c * HWD);
        ull xp0 = packf2(x.x, x.y);
        ull xp1 = packf2(x.z, x.w);
#pragma unroll
        for (int d = 0; d < 16; d++) {
            ull w = wrow[d * 128 + c];
            ffma2(acc0[d], w, xp0);
            ffma2(acc1[d], w, xp1);
        }
    }

    float* op = g_mpart[chunk] + ((size_t)b * DD + dh * 16) * HWD + px;
#pragma unroll
    for (int d = 0; d < 16; d++) {
        float a, bb_, c, dd_;
        unpackf2(a, bb_, acc0[d]);
        unpackf2(c, dd_, acc1[d]);
        *reinterpret_cast<float2*>(op + (size_t)d * HWD)     = make_float2(a, bb_);
        *reinterpret_cast<float2*>(op + (size_t)d * HWD + 2) = make_float2(c, dd_);
    }
}

// ---------------------------------------------------------------------------
// Kernel 1b: combine partials -> maxout, qmax, qmean.  (parallel version)
// Grid: (B*HWD)/64 blocks x 512 threads.  Thread = (pixel 0..63, dgroup 0..7),
// each handling 4 d's.  Smem reduce (max,sum) over the 8 dgroups.
// ---------------------------------------------------------------------------
__global__ void __launch_bounds__(512)
k_maxcomb(const float* __restrict__ ksa_b)
{
    __shared__ float smx[8][64];
    __shared__ float ssm[8][64];
    int tid = threadIdx.x;
    int pl = tid & 63;               // pixel lane
    int dg = tid >> 6;               // d group (0..7)
    int gp = blockIdx.x * 64 + pl;   // global pixel in [0, B*HWD)
    int b = gp >> 12;
    int p = gp & (HWD - 1);

    float mx = -1e30f, sm = 0.f;
#pragma unroll
    for (int k = 0; k < 4; k++) {
        int d = dg * 4 + k;
        size_t off = ((size_t)b * DD + d) * HWD + p;
        float v = ksa_b[d] + g_mpart[0][off] + g_mpart[1][off]
                           + g_mpart[2][off] + g_mpart[3][off];
        g_maxout[off] = v;
        mx = fmaxf(mx, v);
        sm += v;
    }
    smx[dg][pl] = mx;
    ssm[dg][pl] = sm;
    __syncthreads();

    if (dg == 0) {
        float m = smx[0][pl], s = ssm[0][pl];
#pragma unroll
        for (int g = 1; g < 8; g++) {
            m = fmaxf(m, smx[g][pl]);
            s += ssm[g][pl];
        }
        g_qmax [gp] = m;
        g_qmean[gp] = s * (1.f / 32.f);
    }
}

// ---------------------------------------------------------------------------
// Kernel 2a: lit partials (scrambled flat view).
// ---------------------------------------------------------------------------
__global__ void k_lit_a(void)
{
    int chunk = blockIdx.x & 3;
    int bd = blockIdx.x >> 2;
    int d = bd & 31, b = bd >> 5;
    int tid = threadIdx.x;
    const float* mo = g_maxout + (size_t)b * DD * HWD;
    const float* q  = g_qmax + b * HWD;

    float part = 0.f;
#pragma unroll
    for (int k = 0; k < 4; k++) {
        int p = chunk * 1024 + tid + (k << 8);
        part += q[p] * mo[((p >> 7) << 12) + ((p & 127) << 5) + d];
    }
#pragma unroll
    for (int off = 16; off; off >>= 1)
        part += __shfl_xor_sync(0xffffffffu, part, off);

    __shared__ float sred[8];
    if ((tid & 31) == 0) sred[tid >> 5] = part;
    __syncthreads();
    if (tid == 0) {
        float s = 0.f;
#pragma unroll
        for (int w = 0; w < 8; w++) s += sred[w];
        g_litpart[blockIdx.x] = s;
    }
}

// ---------------------------------------------------------------------------
// Kernel 2b: re_score = sum_d lit[d]*mo[d][p]; scale = 1 + sigmoid.
// ---------------------------------------------------------------------------
__global__ void k_lit_b(float* __restrict__ rescore_out)
{
    __shared__ float slit[32];
    int b = blockIdx.y;
    int p = blockIdx.x * 128 + threadIdx.x;
    if (threadIdx.x < 32) {
        const float* lp = g_litpart + (b * DD + threadIdx.x) * 4;
        slit[threadIdx.x] = (lp[0] + lp[1] + lp[2] + lp[3]) * (1.f / 4096.f);
    }
    __syncthreads();

    const float* mo = g_maxout + (size_t)b * DD * HWD;
    float r = 0.f;
#pragma unroll
    for (int d = 0; d < 32; d++) r += slit[d] * mo[d * HWD + p];
    rescore_out[b * HWD + p] = r;
    g_scale[b * HWD + p] = 1.f + 1.f / (1.f + __expf(-r));
}

// ---------------------------------------------------------------------------
// Kernel W: split K_w into bf16 hi/lo.
// ---------------------------------------------------------------------------
__global__ void k_wconv(const float* __restrict__ W)
{
    int i = blockIdx.x * 256 + threadIdx.x;
    float v = W[i];
    __nv_bfloat16 h = __float2bfloat16(v);
    __nv_bfloat16 l = __float2bfloat16(v - __bfloat162float(h));
    g_Whi[i] = h;
    g_Wlo[i] = l;
}

// ---------------------------------------------------------------------------
// Kernel X: elementwise split (native [b][c][p] layout kept).
// ---------------------------------------------------------------------------
__device__ __forceinline__ uint32_t bfpk(__nv_bfloat16 a, __nv_bfloat16 b) {
    __nv_bfloat162 t; t.x = a; t.y = b;
    return *reinterpret_cast<uint32_t*>(&t);
}
__global__ void k_xsplit(const float* __restrict__ X)
{
    size_t i = ((size_t)blockIdx.x * 256 + threadIdx.x) * 8;
    float4 a = *reinterpret_cast<const float4*>(X + i);
    float4 b = *reinterpret_cast<const float4*>(X + i + 4);
    float v[8] = {a.x, a.y, a.z, a.w, b.x, b.y, b.z, b.w};
    __nv_bfloat16 h[8], l[8];
#pragma unroll
    for (int k = 0; k < 8; k++) {
        h[k] = __float2bfloat16(v[k]);
        l[k] = __float2bfloat16(v[k] - __bfloat162float(h[k]));
    }
    uint4 hv = make_uint4(bfpk(h[0], h[1]), bfpk(h[2], h[3]),
                          bfpk(h[4], h[5]), bfpk(h[6], h[7]));
    uint4 lv = make_uint4(bfpk(l[0], l[1]), bfpk(l[2], l[3]),
                          bfpk(l[4], l[5]), bfpk(l[6], l[7]));
    *reinterpret_cast<uint4*>(g_Xhi + i) = hv;
    *reinterpret_cast<uint4*>(g_Xlo + i) = lv;
}

// ---------------------------------------------------------------------------
// Kernel 3: bf16 split GEMM via mma.sync, hi*hi + hi*lo + lo*hi.
// Block 128x128, BK=32, 8 warps, THREE-stage cp.async pipeline.
// ---------------------------------------------------------------------------
#define GBK  32
#define ATB  (128 * 80)               // 10240 per A tile
#define BTB  (32 * 256)               // 8192  per B tile
#define BUFB (2 * ATB + 2 * BTB)      // 36864
#define NSTAGE 3
#define GSMEM (NSTAGE * BUFB)         // 110592

__global__ void __launch_bounds__(256)
k_gemm_mma(const float* __restrict__ bias)
{
    extern __shared__ char smem[];
    const uint32_t sbase = smem_u32(smem);
    const int tid  = threadIdx.x;
    const int lane = tid & 31, wid = tid >> 5;
    const int wm = wid & 1;
    const int wn = wid >> 1;
    const int n0 = blockIdx.x * 128, m0 = blockIdx.y * 128, b = blockIdx.z;

    const __nv_bfloat16* Ahi = g_Whi + (size_t)m0 * CIN;
    const __nv_bfloat16* Alo = g_Wlo + (size_t)m0 * CIN;
    const __nv_bfloat16* Bhi = g_Xhi + (size_t)b * CIN * PIX + n0;
    const __nv_bfloat16* Blo = g_Xlo + (size_t)b * CIN * PIX + n0;

    float acc[4][4][4];
#pragma unroll
    for (int i = 0; i < 4; i++)
#pragma unroll
        for (int j = 0; j < 4; j++)
#pragma unroll
            for (int k = 0; k < 4; k++) acc[i][j][k] = 0.f;

    auto issue = [&](int cidx, int buf) {
        int kc = cidx * GBK;
        uint32_t dbase = sbase + buf * BUFB;
#pragma unroll
        for (int t = 0; t < 2; t++) {
            int s = tid + t * 256;
            {   // A tiles
                int row = s >> 2, seg = s & 3;
                uint32_t doff = row * 80 + seg * 16;
                size_t   soff = (size_t)row * CIN + kc + seg * 8;
                cp16(dbase + doff,       Ahi + soff);
                cp16(dbase + ATB + doff, Alo + soff);
            }
            {   // B tiles, seg-XOR swizzle
                int row = s >> 4, seg = s & 15;
                uint32_t doff = row * 256 + ((seg ^ (row & 7)) << 4);
                size_t   soff = (size_t)(kc + row) * PIX + seg * 8;
                cp16(dbase + 2 * ATB + doff,       Bhi + soff);
                cp16(dbase + 2 * ATB + BTB + doff, Blo + soff);
            }
        }
        asm volatile("cp.async.commit_group;" ::: "memory");
    };

    auto compute = [&](int buf) {
        uint32_t base = sbase + buf * BUFB;
        int l16 = lane & 15;
        int kh8 = (lane >> 4) * 8;
        int krow_base = (lane & 7) + ((lane & 16) >> 1);
        int ncol_base = wn * 32 + (lane & 8);
#pragma unroll
        for (int ks = 0; ks < 2; ks++) {
            int kb = ks * 16 + kh8;
            uint32_t ahi[4][4], alo[4][4];
#pragma unroll
            for (int i = 0; i < 4; i++) {
                uint32_t off = (uint32_t)((wm * 64 + i * 16 + l16) * 80 + kb * 2);
                ldsm4(ahi[i], base + off);
                ldsm4(alo[i], base + ATB + off);
            }
            uint32_t bhi[4][2], blo[4][2];
            {
                int krow = ks * 16 + krow_base;
                uint32_t brow = base + 2 * ATB + krow * 256;
                uint32_t sw = (uint32_t)((krow & 7) << 4);
#pragma unroll
                for (int jj = 0; jj < 2; jj++) {
                    uint32_t boff = ((uint32_t)((ncol_base + jj * 16) * 2)) ^ sw;
                    uint32_t t0[4], t1[4];
                    ldsm4t(t0, brow + boff);
                    ldsm4t(t1, brow + BTB + boff);
                    bhi[jj * 2][0]     = t0[0]; bhi[jj * 2 + 1][0] = t0[1];
                    bhi[jj * 2][1]     = t0[2]; bhi[jj * 2 + 1][1] = t0[3];
                    blo[jj * 2][0]     = t1[0]; blo[jj * 2 + 1][0] = t1[1];
                    blo[jj * 2][1]     = t1[2]; blo[jj * 2 + 1][1] = t1[3];
                }
            }
#pragma unroll
            for (int i = 0; i < 4; i++)
#pragma unroll
                for (int j = 0; j < 4; j++) {
                    mma_bf16(acc[i][j], ahi[i], bhi[j]);
                    mma_bf16(acc[i][j], ahi[i], blo[j]);
                    mma_bf16(acc[i][j], alo[i], bhi[j]);
                }
        }
    };

    issue(0, 0);
    issue(1, 1);
#pragma unroll 1
    for (int c = 0; c < CIN / GBK; c++) {
        asm volatile("cp.async.wait_group 1;" ::: "memory");
        __syncthreads();
        int buf = c % NSTAGE;
        if (c + 2 < CIN / GBK) issue(c + 2, (c + 2) % NSTAGE);
        compute(buf);
        __syncthreads();
    }

    // ---- epilogue: bias + store fp32 ----
    int r = lane >> 2, cpair = (lane & 3) * 2;
    float* Cb = g_Kx + (size_t)b * OC * PIX;
#pragma unroll
    for (int i = 0; i < 4; i++) {
        int m_g = m0 + wm * 64 + i * 16 + r;
        float b0 = bias[m_g], b1 = bias[m_g + 8];
#pragma unroll
        for (int j = 0; j < 4; j++) {
            int n_g = n0 + wn * 32 + j * 8 + cpair;
            float2 v0 = make_float2(acc[i][j][0] + b0, acc[i][j][1] + b0);
            float2 v1 = make_float2(acc[i][j][2] + b1, acc[i][j][3] + b1);
            *reinterpret_cast<float2*>(Cb + (size_t)m_g * PIX + n_g)       = v0;
            *reinterpret_cast<float2*>(Cb + (size_t)(m_g + 8) * PIX + n_g) = v1;
        }
    }
}

// ---------------------------------------------------------------------------
// Kernel 4: fused unfold(3x3, s2, p1) + softmax attention + gating.
// ---------------------------------------------------------------------------
__global__ void k_att(float* __restrict__ out)
{
    int idx = blockIdx.x * 256 + threadIdx.x;
    int p = idx & (HWD - 1);
    int o = (idx >> 12) & (OC - 1);
    int b = idx >> 20;
    int y = p >> 6, x = p & 63;

    const float* base = g_Kx + ((size_t)(b * OC + o) << 14);
    float m  = g_qmean[(b << 12) + p];
    float sc = g_scale[(b << 12) + p];

    float v[9];
    int yy0 = 2 * y - 1, xx0 = 2 * x - 1;
#pragma unroll
    for (int i = 0; i < 3; i++) {
        int yy = yy0 + i;
#pragma unroll
        for (int j = 0; j < 3; j++) {
            int xx = xx0 + j;
            v[i * 3 + j] = (yy >= 0 && xx >= 0) ? base[(yy << 7) + xx] : 0.f;
        }
    }

    float L = m * v[0];
#pragma unroll
    for (int k = 1; k < 9; k++) L = fmaxf(L, m * v[k]);
    float s = 0.f, num = 0.f;
#pragma unroll
    for (int k = 0; k < 9; k++) {
        float e = __expf(m * v[k] - L);
        s   += e;
        num += e * v[k];
    }
    out[idx] = sc * __fdividef(num, s);
}

// ---------------------------------------------------------------------------
extern "C" void kernel_launch(void* const* d_in, const int* in_sizes, int n_in,
                              void* d_out, int out_size)
{
    const float* shallow = (const float*)d_in[0];
    const float* deep    = (const float*)d_in[1];
    const float* K_w     = (const float*)d_in[2];
    const float* K_b     = (const float*)d_in[3];
    const float* KSA_w   = (const float*)d_in[4];
    const float* KSA_b   = (const float*)d_in[5];
    float* out = (float*)d_out;

    float* rescore_out = out + (size_t)BB * OC * HWD;

    cudaFuncSetAttribute(k_gemm_mma, cudaFuncAttributeMaxDynamicSharedMemorySize,
                         GSMEM);

    k_wconv<<<(OC * CIN) / 256, 256>>>(K_w);
    k_xsplit<<<(int)(((size_t)BB * CIN * PIX) / (256 * 8)), 256>>>(shallow);
    k_maxout_part<<<dim3(HWD / 256, BB, 4), 128>>>(deep, KSA_w);
    k_maxcomb<<<(BB * HWD) / 64, 512>>>(KSA_b);
    k_lit_a<<<BB * DD * 4, 256>>>();
    k_lit_b<<<dim3(HWD / 128, BB), 128>>>(rescore_out);
    k_gemm_mma<<<dim3(PIX / 128, OC / 128, BB), 256, GSMEM>>>(K_b);
    k_att<<<(BB * OC * HWD) / 256, 256>>>(out);
}

// round 16
// speedup vs baseline: 3.0849x; 1.1688x over previous
#include <cuda_runtime.h>
#include <cuda_bf16.h>
#include <cuda_fp16.h>
#include <math.h>
#include <stdint.h>

// Problem constants (fixed by setup_inputs)
#define BB   4
#define C2   512        // deep channels
#define DD   32         // d = 2*C/16
#define HWD  4096       // 64*64 deep spatial
#define OC   256        // out channels of K conv
#define CIN  256        // shallow channels
#define PIX  16384      // 128*128 shallow spatial

typedef unsigned long long ull;

// Scratch (device globals: allocation-free)
__device__ float g_maxout[BB * DD * HWD];
__device__ float g_mpart[4][BB * DD * HWD];                            // split-K partials
__device__ float g_qmax [BB * HWD];
__device__ float g_qmean[BB * HWD];
__device__ float g_scale[BB * HWD];
__device__ float g_litpart[BB * DD * 4];
__device__ float g_Kx[(size_t)BB * OC * PIX];                          // 64MB
__device__ __align__(16) __half g_Whi[OC * CIN];                       // fp16 weight hi
__device__ __align__(16) __half g_Wlo[OC * CIN];                       // fp16 weight lo
__device__ __align__(16) __half g_Xh[(size_t)BB * CIN * PIX];          // fp16 shallow, [b][c][p]

// ---------------------------------------------------------------------------
// PTX helpers
// ---------------------------------------------------------------------------
__device__ __forceinline__ uint32_t smem_u32(const void* p) {
    uint32_t a;
    asm("{ .reg .u64 t; cvta.to.shared.u64 t, %1; cvt.u32.u64 %0, t; }"
        : "=r"(a) : "l"(p));
    return a;
}
__device__ __forceinline__ void cp16(uint32_t dst, const void* src) {
    asm volatile("cp.async.cg.shared.global [%0], [%1], 16;"
                 :: "r"(dst), "l"(src) : "memory");
}
__device__ __forceinline__ void ldsm4(uint32_t* r, uint32_t addr) {
    asm volatile("ldmatrix.sync.aligned.m8n8.x4.shared.b16 {%0,%1,%2,%3}, [%4];"
                 : "=r"(r[0]), "=r"(r[1]), "=r"(r[2]), "=r"(r[3]) : "r"(addr));
}
__device__ __forceinline__ void ldsm4t(uint32_t* r, uint32_t addr) {
    asm volatile("ldmatrix.sync.aligned.m8n8.x4.trans.shared.b16 {%0,%1,%2,%3}, [%4];"
                 : "=r"(r[0]), "=r"(r[1]), "=r"(r[2]), "=r"(r[3]) : "r"(addr));
}
__device__ __forceinline__ void mma_f16(float* c, const uint32_t* a, const uint32_t* b) {
    asm volatile(
        "mma.sync.aligned.m16n8k16.row.col.f32.f16.f16.f32 "
        "{%0,%1,%2,%3}, {%4,%5,%6,%7}, {%8,%9}, {%0,%1,%2,%3};"
        : "+f"(c[0]), "+f"(c[1]), "+f"(c[2]), "+f"(c[3])
        : "r"(a[0]), "r"(a[1]), "r"(a[2]), "r"(a[3]), "r"(b[0]), "r"(b[1]));
}
__device__ __forceinline__ void ffma2(ull& d, ull a, ull b) {
    asm("fma.rn.f32x2 %0, %1, %2, %0;" : "+l"(d) : "l"(a), "l"(b));
}
__device__ __forceinline__ ull packf2(float lo, float hi) {
    ull v; asm("mov.b64 %0, {%1, %2};" : "=l"(v) : "f"(lo), "f"(hi)); return v;
}
__device__ __forceinline__ void unpackf2(float& lo, float& hi, ull v) {
    asm("mov.b64 {%0, %1}, %2;" : "=f"(lo), "=f"(hi) : "l"(v));
}

// ---------------------------------------------------------------------------
// Kernel 1a: partial max_out over a 128-channel chunk (split-K x4), FFMA2.
// ---------------------------------------------------------------------------
__global__ void __launch_bounds__(128)
k_maxout_part(const float* __restrict__ deep, const float* __restrict__ ksa_w)
{
    __shared__ ull ws2[32 * 128];   // 32KB, dup-packed (w,w)
    int b = blockIdx.y, chunk = blockIdx.z;
    int tid = threadIdx.x;
    int dh = tid & 1;               // d half
    int pq = tid >> 1;              // pixel quad 0..63
    int px = blockIdx.x * 256 + pq * 4;

    for (int i = tid; i < 32 * 128; i += 128) {
        int d = i >> 7, c = i & 127;
        float w = ksa_w[d * C2 + chunk * 128 + c];
        ws2[i] = packf2(w, w);
    }
    __syncthreads();

    ull acc0[16], acc1[16];
#pragma unroll
    for (int d = 0; d < 16; d++) { acc0[d] = 0ull; acc1[d] = 0ull; }

    const float* dp = deep + ((size_t)b * C2 + chunk * 128) * HWD + px;
    const ull* wrow = ws2 + (dh * 16) * 128;
#pragma unroll 2
    for (int c = 0; c < 128; c++) {
        float4 x = *reinterpret_cast<const float4*>(dp + (size_t)c * HWD);
        ull xp0 = packf2(x.x, x.y);
        ull xp1 = packf2(x.z, x.w);
#pragma unroll
        for (int d = 0; d < 16; d++) {
            ull w = wrow[d * 128 + c];
            ffma2(acc0[d], w, xp0);
            ffma2(acc1[d], w, xp1);
        }
    }

    float* op = g_mpart[chunk] + ((size_t)b * DD + dh * 16) * HWD + px;
#pragma unroll
    for (int d = 0; d < 16; d++) {
        float a, bb_, c, dd_;
        unpackf2(a, bb_, acc0[d]);
        unpackf2(c, dd_, acc1[d]);
        *reinterpret_cast<float2*>(op + (size_t)d * HWD)     = make_float2(a, bb_);
        *reinterpret_cast<float2*>(op + (size_t)d * HWD + 2) = make_float2(c, dd_);
    }
}

// ---------------------------------------------------------------------------
// Kernel 1b: combine partials -> maxout, qmax, qmean (parallel).
// ---------------------------------------------------------------------------
__global__ void __launch_bounds__(512)
k_maxcomb(const float* __restrict__ ksa_b)
{
    __shared__ float smx[8][64];
    __shared__ float ssm[8][64];
    int tid = threadIdx.x;
    int pl = tid & 63;
    int dg = tid >> 6;
    int gp = blockIdx.x * 64 + pl;
    int b = gp >> 12;
    int p = gp & (HWD - 1);

    float mx = -1e30f, sm = 0.f;
#pragma unroll
    for (int k = 0; k < 4; k++) {
        int d = dg * 4 + k;
        size_t off = ((size_t)b * DD + d) * HWD + p;
        float v = ksa_b[d] + g_mpart[0][off] + g_mpart[1][off]
                           + g_mpart[2][off] + g_mpart[3][off];
        g_maxout[off] = v;
        mx = fmaxf(mx, v);
        sm += v;
    }
    smx[dg][pl] = mx;
    ssm[dg][pl] = sm;
    __syncthreads();

    if (dg == 0) {
        float m = smx[0][pl], s = ssm[0][pl];
#pragma unroll
        for (int g = 1; g < 8; g++) {
            m = fmaxf(m, smx[g][pl]);
            s += ssm[g][pl];
        }
        g_qmax [gp] = m;
        g_qmean[gp] = s * (1.f / 32.f);
    }
}

// ---------------------------------------------------------------------------
// Kernel 2a: lit partials (scrambled flat view).
// ---------------------------------------------------------------------------
__global__ void k_lit_a(void)
{
    int chunk = blockIdx.x & 3;
    int bd = blockIdx.x >> 2;
    int d = bd & 31, b = bd >> 5;
    int tid = threadIdx.x;
    const float* mo = g_maxout + (size_t)b * DD * HWD;
    const float* q  = g_qmax + b * HWD;

    float part = 0.f;
#pragma unroll
    for (int k = 0; k < 4; k++) {
        int p = chunk * 1024 + tid + (k << 8);
        part += q[p] * mo[((p >> 7) << 12) + ((p & 127) << 5) + d];
    }
#pragma unroll
    for (int off = 16; off; off >>= 1)
        part += __shfl_xor_sync(0xffffffffu, part, off);

    __shared__ float sred[8];
    if ((tid & 31) == 0) sred[tid >> 5] = part;
    __syncthreads();
    if (tid == 0) {
        float s = 0.f;
#pragma unroll
        for (int w = 0; w < 8; w++) s += sred[w];
        g_litpart[blockIdx.x] = s;
    }
}

// ---------------------------------------------------------------------------
// Kernel 2b: re_score = sum_d lit[d]*mo[d][p]; scale = 1 + sigmoid.
// ---------------------------------------------------------------------------
__global__ void k_lit_b(float* __restrict__ rescore_out)
{
    __shared__ float slit[32];
    int b = blockIdx.y;
    int p = blockIdx.x * 128 + threadIdx.x;
    if (threadIdx.x < 32) {
        const float* lp = g_litpart + (b * DD + threadIdx.x) * 4;
        slit[threadIdx.x] = (lp[0] + lp[1] + lp[2] + lp[3]) * (1.f / 4096.f);
    }
    __syncthreads();

    const float* mo = g_maxout + (size_t)b * DD * HWD;
    float r = 0.f;
#pragma unroll
    for (int d = 0; d < 32; d++) r += slit[d] * mo[d * HWD + p];
    rescore_out[b * HWD + p] = r;
    g_scale[b * HWD + p] = 1.f + 1.f / (1.f + __expf(-r));
}

// ---------------------------------------------------------------------------
// Kernel W: split K_w into fp16 hi/lo (11+11 mantissa bits).
// ---------------------------------------------------------------------------
__global__ void k_wconv(const float* __restrict__ W)
{
    int i = blockIdx.x * 256 + threadIdx.x;
    float v = W[i];
    __half h = __float2half_rn(v);
    __half l = __float2half_rn(v - __half2float(h));
    g_Whi[i] = h;
    g_Wlo[i] = l;
}

// ---------------------------------------------------------------------------
// Kernel X: convert shallow to fp16 (single tensor, native [b][c][p] layout).
// ---------------------------------------------------------------------------
__global__ void k_xsplit(const float* __restrict__ X)
{
    size_t i = ((size_t)blockIdx.x * 256 + threadIdx.x) * 8;
    float4 a = *reinterpret_cast<const float4*>(X + i);
    float4 b = *reinterpret_cast<const float4*>(X + i + 4);
    __half2 h0 = __floats2half2_rn(a.x, a.y);
    __half2 h1 = __floats2half2_rn(a.z, a.w);
    __half2 h2 = __floats2half2_rn(b.x, b.y);
    __half2 h3 = __floats2half2_rn(b.z, b.w);
    uint4 hv = make_uint4(*reinterpret_cast<uint32_t*>(&h0),
                          *reinterpret_cast<uint32_t*>(&h1),
                          *reinterpret_cast<uint32_t*>(&h2),
                          *reinterpret_cast<uint32_t*>(&h3));
    *reinterpret_cast<uint4*>(g_Xh + i) = hv;
}

// ---------------------------------------------------------------------------
// Kernel 3: fp16 split GEMM via mma.sync: C = (Ahi + Alo) * B,  2 MMAs/tile.
// Block 128x128, BK=32, 8 warps, 3-stage cp.async pipeline.
// A tiles [m][k] pitch-80B; B tile [k][n] 256B rows, seg-XOR swizzle,
// consumed by ldmatrix.x4.trans from X's native [c][p] layout.
// ---------------------------------------------------------------------------
#define GBK  32
#define ATB  (128 * 80)               // 10240 per A tile
#define BTB  (32 * 256)               // 8192  B tile
#define BUFB (2 * ATB + BTB)          // 28672
#define NSTAGE 3
#define GSMEM (NSTAGE * BUFB)         // 86016

__global__ void __launch_bounds__(256)
k_gemm_mma(const float* __restrict__ bias)
{
    extern __shared__ char smem[];
    const uint32_t sbase = smem_u32(smem);
    const int tid  = threadIdx.x;
    const int lane = tid & 31, wid = tid >> 5;
    const int wm = wid & 1;
    const int wn = wid >> 1;
    const int n0 = blockIdx.x * 128, m0 = blockIdx.y * 128, b = blockIdx.z;

    const __half* Ahi = g_Whi + (size_t)m0 * CIN;
    const __half* Alo = g_Wlo + (size_t)m0 * CIN;
    const __half* Bx  = g_Xh + (size_t)b * CIN * PIX + n0;

    float acc[4][4][4];
#pragma unroll
    for (int i = 0; i < 4; i++)
#pragma unroll
        for (int j = 0; j < 4; j++)
#pragma unroll
            for (int k = 0; k < 4; k++) acc[i][j][k] = 0.f;

    auto issue = [&](int cidx, int buf) {
        int kc = cidx * GBK;
        uint32_t dbase = sbase + buf * BUFB;
#pragma unroll
        for (int t = 0; t < 2; t++) {
            int s = tid + t * 256;
            {   // A tiles: 128 rows x 4 segs of 16B
                int row = s >> 2, seg = s & 3;
                uint32_t doff = row * 80 + seg * 16;
                size_t   soff = (size_t)row * CIN + kc + seg * 8;
                cp16(dbase + doff,       Ahi + soff);
                cp16(dbase + ATB + doff, Alo + soff);
            }
            {   // B tile: 32 k-rows x 16 segs of 16B, seg-XOR swizzle
                int row = s >> 4, seg = s & 15;
                uint32_t doff = row * 256 + ((seg ^ (row & 7)) << 4);
                size_t   soff = (size_t)(kc + row) * PIX + seg * 8;
                cp16(dbase + 2 * ATB + doff, Bx + soff);
            }
        }
        asm volatile("cp.async.commit_group;" ::: "memory");
    };

    auto compute = [&](int buf) {
        uint32_t base = sbase + buf * BUFB;
        int l16 = lane & 15;
        int kh8 = (lane >> 4) * 8;
        int krow_base = (lane & 7) + ((lane & 16) >> 1);
        int ncol_base = wn * 32 + (lane & 8);
#pragma unroll
        for (int ks = 0; ks < 2; ks++) {
            int kb = ks * 16 + kh8;
            uint32_t ahi[4][4], alo[4][4];
#pragma unroll
            for (int i = 0; i < 4; i++) {
                uint32_t off = (uint32_t)((wm * 64 + i * 16 + l16) * 80 + kb * 2);
                ldsm4(ahi[i], base + off);
                ldsm4(alo[i], base + ATB + off);
            }
            uint32_t bfr[4][2];
            {
                int krow = ks * 16 + krow_base;
                uint32_t brow = base + 2 * ATB + krow * 256;
                uint32_t sw = (uint32_t)((krow & 7) << 4);
#pragma unroll
                for (int jj = 0; jj < 2; jj++) {
                    uint32_t boff = ((uint32_t)((ncol_base + jj * 16) * 2)) ^ sw;
                    uint32_t t0[4];
                    ldsm4t(t0, brow + boff);
                    bfr[jj * 2][0]     = t0[0]; bfr[jj * 2 + 1][0] = t0[1];
                    bfr[jj * 2][1]     = t0[2]; bfr[jj * 2 + 1][1] = t0[3];
                }
            }
#pragma unroll
            for (int i = 0; i < 4; i++)
#pragma unroll
                for (int j = 0; j < 4; j++) {
                    mma_f16(acc[i][j], ahi[i], bfr[j]);
                    mma_f16(acc[i][j], alo[i], bfr[j]);
                }
        }
    };

    issue(0, 0);
    issue(1, 1);
#pragma unroll 1
    for (int c = 0; c < CIN / GBK; c++) {
        asm volatile("cp.async.wait_group 1;" ::: "memory");
        __syncthreads();
        if (c + 2 < CIN / GBK) issue(c + 2, (c + 2) % NSTAGE);
        compute(c % NSTAGE);
    }

    // ---- epilogue: bias + store fp32 ----
    int r = lane >> 2, cpair = (lane & 3) * 2;
    float* Cb = g_Kx + (size_t)b * OC * PIX;
#pragma unroll
    for (int i = 0; i < 4; i++) {
        int m_g = m0 + wm * 64 + i * 16 + r;
        float b0 = bias[m_g], b1 = bias[m_g + 8];
#pragma unroll
        for (int j = 0; j < 4; j++) {
            int n_g = n0 + wn * 32 + j * 8 + cpair;
            float2 v0 = make_float2(acc[i][j][0] + b0, acc[i][j][1] + b0);
            float2 v1 = make_float2(acc[i][j][2] + b1, acc[i][j][3] + b1);
            *reinterpret_cast<float2*>(Cb + (size_t)m_g * PIX + n_g)       = v0;
            *reinterpret_cast<float2*>(Cb + (size_t)(m_g + 8) * PIX + n_g) = v1;
        }
    }
}

// ---------------------------------------------------------------------------
// Kernel 4: fused unfold(3x3, s2, p1) + softmax attention + gating.
// ---------------------------------------------------------------------------
__global__ void k_att(float* __restrict__ out)
{
    int idx = blockIdx.x * 256 + threadIdx.x;
    int p = idx & (HWD - 1);
    int o = (idx >> 12) & (OC - 1);
    int b = idx >> 20;
    int y = p >> 6, x = p & 63;

    const float* base = g_Kx + ((size_t)(b * OC + o) << 14);
    float m  = g_qmean[(b << 12) + p];
    float sc = g_scale[(b << 12) + p];

    float v[9];
    int yy0 = 2 * y - 1, xx0 = 2 * x - 1;
#pragma unroll
    for (int i = 0; i < 3; i++) {
        int yy = yy0 + i;
#pragma unroll
        for (int j = 0; j < 3; j++) {
            int xx = xx0 + j;
            v[i * 3 + j] = (yy >= 0 && xx >= 0) ? base[(yy << 7) + xx] : 0.f;
        }
    }

    float L = m * v[0];
#pragma unroll
    for (int k = 1; k < 9; k++) L = fmaxf(L, m * v[k]);
    float s = 0.f, num = 0.f;
#pragma unroll
    for (int k = 0; k < 9; k++) {
        float e = __expf(m * v[k] - L);
        s   += e;
        num += e * v[k];
    }
    out[idx] = sc * __fdividef(num, s);
}

// ---------------------------------------------------------------------------
extern "C" void kernel_launch(void* const* d_in, const int* in_sizes, int n_in,
                              void* d_out, int out_size)
{
    const float* shallow = (const float*)d_in[0];
    const float* deep    = (const float*)d_in[1];
    const float* K_w     = (const float*)d_in[2];
    const float* K_b     = (const float*)d_in[3];
    const float* KSA_w   = (const float*)d_in[4];
    const float* KSA_b   = (const float*)d_in[5];
    float* out = (float*)d_out;

    float* rescore_out = out + (size_t)BB * OC * HWD;

    cudaFuncSetAttribute(k_gemm_mma, cudaFuncAttributeMaxDynamicSharedMemorySize,
                         GSMEM);

    // Note: k_gemm_mma placed 4th — ncu captures launch #4 (-s 5 -c 1 pattern);
    // dependencies still respected (gemm needs only wconv + xsplit).
    k_wconv<<<(OC * CIN) / 256, 256>>>(K_w);
    k_xsplit<<<(int)(((size_t)BB * CIN * PIX) / (256 * 8)), 256>>>(shallow);
    k_maxout_part<<<dim3(HWD / 256, BB, 4), 128>>>(deep, KSA_w);
    k_gemm_mma<<<dim3(PIX / 128, OC / 128, BB), 256, GSMEM>>>(K_b);
    k_maxcomb<<<(BB * HWD) / 64, 512>>>(KSA_b);
    k_lit_a<<<BB * DD * 4, 256>>>();
    k_lit_b<<<dim3(HWD / 128, BB), 128>>>(rescore_out);
    k_att<<<(BB * OC * HWD) / 256, 256>>>(out);
}